// round 6
// baseline (speedup 1.0000x reference)
#include <cuda_runtime.h>
#include <math.h>

#define N_NODES 16384
#define N_EDGES 262144
#define DIM 256          // D_IN == D == 256
#define HID 512
#define NEXP 64
#define CAP 1024
#define NSLOT (NEXP * CAP)   // 65536
#define BN_EPS 1e-5f

// ---------------- scratch (device globals; no allocation allowed) ----------------
__device__ int   g_deg_out[N_NODES];
__device__ int   g_deg_in[N_NODES];
__device__ float g_rs_out[N_NODES];
__device__ float g_rs_in[N_NODES];
__device__ float g_m[N_NODES * DIM];          // 16 MB  (aggregated messages)
__device__ float g_x[N_NODES * DIM];          // 16 MB  (post-residual features)
__device__ int   g_counts[NEXP];
__device__ int   g_tok[NSLOT];                // token id per expert slot
__device__ int   g_pair_slot[N_NODES * 2];
__device__ float g_pair_gate[N_NODES * 2];
__device__ float g_h1[(size_t)NSLOT * HID];   // 128 MB (expert hidden)
__device__ float g_h2[(size_t)NSLOT * DIM];   // 64 MB  (expert out)
__device__ float g_y[N_NODES * DIM];          // 16 MB  (pre-BN)
__device__ float g_colsum[DIM];
__device__ float g_colsumsq[DIM];

// ---------------- zero everything that is accumulated ----------------
__global__ void k_zero() {
    int idx = blockIdx.x * blockDim.x + threadIdx.x;
    int stride = gridDim.x * blockDim.x;
    for (int i = idx; i < N_NODES * DIM; i += stride) g_m[i] = 0.f;
    if (idx < N_NODES) { g_deg_out[idx] = 0; g_deg_in[idx] = 0; }
    if (idx < NEXP) g_counts[idx] = 0;
    if (idx < DIM) { g_colsum[idx] = 0.f; g_colsumsq[idx] = 0.f; }
}

// ---------------- degree counts ----------------
__global__ void k_deg(const int* __restrict__ src, const int* __restrict__ dst) {
    int e = blockIdx.x * blockDim.x + threadIdx.x;
    if (e < N_EDGES) {
        atomicAdd(&g_deg_out[src[e]], 1);
        atomicAdd(&g_deg_in[dst[e]], 1);
    }
}

__global__ void k_rs() {
    int i = blockIdx.x * blockDim.x + threadIdx.x;
    if (i < N_NODES) {
        g_rs_out[i] = rsqrtf((float)max(g_deg_out[i], 1));
        g_rs_in[i]  = rsqrtf((float)max(g_deg_in[i], 1));
    }
}

// ---------------- edge scatter: m[dst] += feats[src] * rs_out[src] ----------------
// one warp per edge; vectorized red.global.add.v4.f32 (sm_90+)
__global__ void k_scatter(const float* __restrict__ feats,
                          const int* __restrict__ src, const int* __restrict__ dst) {
    int warp = (blockIdx.x * blockDim.x + threadIdx.x) >> 5;
    int lane = threadIdx.x & 31;
    if (warp >= N_EDGES) return;
    int s = src[warp], d = dst[warp];
    float sc = g_rs_out[s];
    const float4* fr = (const float4*)(feats + (size_t)s * DIM);
    float* mr = g_m + (size_t)d * DIM;
#pragma unroll
    for (int i = 0; i < 2; i++) {
        int j = lane + i * 32;           // 64 float4 per row
        float4 v = __ldg(&fr[j]);
        v.x *= sc; v.y *= sc; v.z *= sc; v.w *= sc;
        asm volatile("red.global.add.v4.f32 [%0], {%1,%2,%3,%4};"
                     :: "l"(mr + j * 4), "f"(v.x), "f"(v.y), "f"(v.z), "f"(v.w)
                     : "memory");
    }
}

// ---------------- GEMM tiles: 64x128, BK=32, 256 threads, 4x8 micro ----------------
#define BM 64
#define BN 128
#define BK 32

// x = (m * rs_in) @ W_gc + feats @ W_res + b_gc + b_res   (K = 512 fused)
__global__ __launch_bounds__(256) void k_xgemm(
    const float* __restrict__ feats,
    const float* __restrict__ Wgc, const float* __restrict__ bgc,
    const float* __restrict__ Wres, const float* __restrict__ bres) {
    __shared__ float As[BK][BM + 4];
    __shared__ float Bs[BK][BN];
    int row0 = blockIdx.y * BM;
    int col0 = blockIdx.x * BN;
    int tid = threadIdx.x;
    int tx = tid & 15, ty = tid >> 4;
    int r0 = ty * 4, c0 = tx * 8;
    float acc[4][8];
#pragma unroll
    for (int i = 0; i < 4; i++)
#pragma unroll
        for (int j = 0; j < 8; j++) acc[i][j] = 0.f;

    for (int kb = 0; kb < 2 * DIM; kb += BK) {
        const float* A; const float* B; int kbase; bool scaled;
        if (kb < DIM) { A = g_m;  B = Wgc;  kbase = kb;       scaled = true;  }
        else          { A = feats; B = Wres; kbase = kb - DIM; scaled = false; }
#pragma unroll
        for (int i = 0; i < 8; i++) {
            int idx = tid + i * 256;
            int r = idx >> 5, k = idx & 31;
            float v = A[(size_t)(row0 + r) * DIM + kbase + k];
            if (scaled) v *= g_rs_in[row0 + r];
            As[k][r] = v;
        }
#pragma unroll
        for (int i = 0; i < 16; i++) {
            int idx = tid + i * 256;
            int kk = idx >> 7, c = idx & 127;
            Bs[kk][c] = B[(size_t)(kbase + kk) * DIM + col0 + c];
        }
        __syncthreads();
#pragma unroll
        for (int kk = 0; kk < BK; kk++) {
            float a[4], b[8];
#pragma unroll
            for (int i = 0; i < 4; i++) a[i] = As[kk][r0 + i];
#pragma unroll
            for (int j = 0; j < 8; j++) b[j] = Bs[kk][c0 + j];
#pragma unroll
            for (int i = 0; i < 4; i++)
#pragma unroll
                for (int j = 0; j < 8; j++) acc[i][j] = fmaf(a[i], b[j], acc[i][j]);
        }
        __syncthreads();
    }
#pragma unroll
    for (int i = 0; i < 4; i++) {
        int r = row0 + r0 + i;
#pragma unroll
        for (int j = 0; j < 8; j++) {
            int c = col0 + c0 + j;
            g_x[(size_t)r * DIM + c] = acc[i][j] + bgc[c] + bres[c];
        }
    }
}

// ---------------- gating: warp per token, top-2 + softmax, slot assignment ----------------
__global__ void k_gate(const float* __restrict__ Wg, const float* __restrict__ bg) {
    int t = (blockIdx.x * blockDim.x + threadIdx.x) >> 5;
    int lane = threadIdx.x & 31;
    if (t >= N_NODES) return;
    const float* xr = g_x + (size_t)t * DIM;
    float la = bg[lane], lb = bg[lane + 32];
    for (int k = 0; k < DIM; k++) {
        float xv = xr[k];                        // warp-uniform broadcast
        la = fmaf(xv, Wg[k * NEXP + lane], la);
        lb = fmaf(xv, Wg[k * NEXP + lane + 32], lb);
    }
    // top-1 (lower index wins ties, matching lax.top_k)
    float bv = la; int bi = lane;
    if (lb > bv) { bv = lb; bi = lane + 32; }
#pragma unroll
    for (int off = 16; off; off >>= 1) {
        float ov = __shfl_xor_sync(0xffffffffu, bv, off);
        int   oi = __shfl_xor_sync(0xffffffffu, bi, off);
        if (ov > bv || (ov == bv && oi < bi)) { bv = ov; bi = oi; }
    }
    float v0 = bv; int e0 = bi;
    // top-2
    float ca = (lane == e0) ? -INFINITY : la;
    float cb = (lane + 32 == e0) ? -INFINITY : lb;
    float bv2 = ca; int bi2 = lane;
    if (cb > bv2) { bv2 = cb; bi2 = lane + 32; }
#pragma unroll
    for (int off = 16; off; off >>= 1) {
        float ov = __shfl_xor_sync(0xffffffffu, bv2, off);
        int   oi = __shfl_xor_sync(0xffffffffu, bi2, off);
        if (ov > bv2 || (ov == bv2 && oi < bi2)) { bv2 = ov; bi2 = oi; }
    }
    float v1 = bv2; int e1 = bi2;
    if (lane == 0) {
        float g0 = 1.f / (1.f + expf(v1 - v0));
        float g1 = 1.f - g0;
        int r0 = atomicAdd(&g_counts[e0], 1);
        int s0 = (r0 < CAP) ? e0 * CAP + r0 : -1;
        if (s0 >= 0) g_tok[s0] = t;
        g_pair_slot[2 * t] = s0; g_pair_gate[2 * t] = g0;
        int r1 = atomicAdd(&g_counts[e1], 1);
        int s1 = (r1 < CAP) ? e1 * CAP + r1 : -1;
        if (s1 >= 0) g_tok[s1] = t;
        g_pair_slot[2 * t + 1] = s1; g_pair_gate[2 * t + 1] = g1;
    }
}

// ---------------- expert FFN stage 1: h1 = gelu(x_gathered @ w1[e] + b1[e]) ----------------
__global__ __launch_bounds__(256) void k_ffn1(const float* __restrict__ w1,
                                              const float* __restrict__ b1) {
    int e = blockIdx.z;
    int cnt = min(g_counts[e], CAP);
    int row0 = blockIdx.y * BM;
    if (row0 >= cnt) return;
    int col0 = blockIdx.x * BN;
    const float* B = w1 + (size_t)e * DIM * HID;    // [DIM][HID]
    __shared__ float As[BK][BM + 4];
    __shared__ float Bs[BK][BN];
    __shared__ int stok[BM];
    int tid = threadIdx.x;
    if (tid < BM) {
        int rr = row0 + tid;
        stok[tid] = (rr < cnt) ? g_tok[e * CAP + rr] : 0;
    }
    __syncthreads();
    int tx = tid & 15, ty = tid >> 4;
    int r0 = ty * 4, c0 = tx * 8;
    float acc[4][8];
#pragma unroll
    for (int i = 0; i < 4; i++)
#pragma unroll
        for (int j = 0; j < 8; j++) acc[i][j] = 0.f;

    for (int kb = 0; kb < DIM; kb += BK) {
#pragma unroll
        for (int i = 0; i < 8; i++) {
            int idx = tid + i * 256;
            int r = idx >> 5, k = idx & 31;
            As[k][r] = g_x[(size_t)stok[r] * DIM + kb + k];
        }
#pragma unroll
        for (int i = 0; i < 16; i++) {
            int idx = tid + i * 256;
            int kk = idx >> 7, c = idx & 127;
            Bs[kk][c] = B[(size_t)(kb + kk) * HID + col0 + c];
        }
        __syncthreads();
#pragma unroll
        for (int kk = 0; kk < BK; kk++) {
            float a[4], b[8];
#pragma unroll
            for (int i = 0; i < 4; i++) a[i] = As[kk][r0 + i];
#pragma unroll
            for (int j = 0; j < 8; j++) b[j] = Bs[kk][c0 + j];
#pragma unroll
            for (int i = 0; i < 4; i++)
#pragma unroll
                for (int j = 0; j < 8; j++) acc[i][j] = fmaf(a[i], b[j], acc[i][j]);
        }
        __syncthreads();
    }
#pragma unroll
    for (int i = 0; i < 4; i++) {
        int rr = row0 + r0 + i;
        if (rr < cnt) {
#pragma unroll
            for (int j = 0; j < 8; j++) {
                int c = col0 + c0 + j;
                float v = acc[i][j] + b1[e * HID + c];
                // exact GELU: 0.5*v*(1+erf(v/sqrt(2)))
                float gl = 0.5f * v * (1.f + erff(v * 0.70710678118654752440f));
                g_h1[(size_t)(e * CAP + rr) * HID + c] = gl;
            }
        }
    }
}

// ---------------- expert FFN stage 2: h2 = h1 @ w2[e] + b2[e] ----------------
__global__ __launch_bounds__(256) void k_ffn2(const float* __restrict__ w2,
                                              const float* __restrict__ b2) {
    int e = blockIdx.z;
    int cnt = min(g_counts[e], CAP);
    int row0 = blockIdx.y * BM;
    if (row0 >= cnt) return;
    int col0 = blockIdx.x * BN;
    const float* B = w2 + (size_t)e * HID * DIM;    // [HID][DIM]
    __shared__ float As[BK][BM + 4];
    __shared__ float Bs[BK][BN];
    int tid = threadIdx.x;
    int tx = tid & 15, ty = tid >> 4;
    int r0 = ty * 4, c0 = tx * 8;
    float acc[4][8];
#pragma unroll
    for (int i = 0; i < 4; i++)
#pragma unroll
        for (int j = 0; j < 8; j++) acc[i][j] = 0.f;

    for (int kb = 0; kb < HID; kb += BK) {
#pragma unroll
        for (int i = 0; i < 8; i++) {
            int idx = tid + i * 256;
            int r = idx >> 5, k = idx & 31;
            As[k][r] = g_h1[(size_t)(e * CAP + row0 + r) * HID + kb + k];
        }
#pragma unroll
        for (int i = 0; i < 16; i++) {
            int idx = tid + i * 256;
            int kk = idx >> 7, c = idx & 127;
            Bs[kk][c] = B[(size_t)(kb + kk) * DIM + col0 + c];
        }
        __syncthreads();
#pragma unroll
        for (int kk = 0; kk < BK; kk++) {
            float a[4], b[8];
#pragma unroll
            for (int i = 0; i < 4; i++) a[i] = As[kk][r0 + i];
#pragma unroll
            for (int j = 0; j < 8; j++) b[j] = Bs[kk][c0 + j];
#pragma unroll
            for (int i = 0; i < 4; i++)
#pragma unroll
                for (int j = 0; j < 8; j++) acc[i][j] = fmaf(a[i], b[j], acc[i][j]);
        }
        __syncthreads();
    }
#pragma unroll
    for (int i = 0; i < 4; i++) {
        int rr = row0 + r0 + i;
        if (rr < cnt) {
#pragma unroll
            for (int j = 0; j < 8; j++) {
                int c = col0 + c0 + j;
                g_h2[(size_t)(e * CAP + rr) * DIM + c] = acc[i][j] + b2[e * DIM + c];
            }
        }
    }
}

// ---------------- combine: y = x + g0*h2[s0] + g1*h2[s1]; column sums for BN ----------------
__global__ void k_combine() {
    int c = threadIdx.x;                 // 256 threads = 256 columns
    int t0 = blockIdx.x * 128;
    float sum = 0.f, sumsq = 0.f;
    for (int i = 0; i < 128; i++) {
        int t = t0 + i;
        int s0 = g_pair_slot[2 * t], s1 = g_pair_slot[2 * t + 1];
        float g0 = g_pair_gate[2 * t], g1 = g_pair_gate[2 * t + 1];
        float v = g_x[(size_t)t * DIM + c];
        if (s0 >= 0) v += g0 * g_h2[(size_t)s0 * DIM + c];
        if (s1 >= 0) v += g1 * g_h2[(size_t)s1 * DIM + c];
        g_y[(size_t)t * DIM + c] = v;
        sum += v; sumsq += v * v;
    }
    atomicAdd(&g_colsum[c], sum);
    atomicAdd(&g_colsumsq[c], sumsq);
}

// ---------------- batchnorm (train-mode, biased var) ----------------
__global__ void k_bn(const float* __restrict__ gamma, const float* __restrict__ beta,
                     float* __restrict__ out) {
    int idx = blockIdx.x * blockDim.x + threadIdx.x;
    if (idx >= N_NODES * DIM) return;
    int c = idx & (DIM - 1);
    const float invN = 1.f / (float)N_NODES;
    float mean = g_colsum[c] * invN;
    float var = g_colsumsq[c] * invN - mean * mean;
    out[idx] = (g_y[idx] - mean) * rsqrtf(var + BN_EPS) * gamma[c] + beta[c];
}

// ---------------- launcher ----------------
extern "C" void kernel_launch(void* const* d_in, const int* in_sizes, int n_in,
                              void* d_out, int out_size) {
    const float* feats = (const float*)d_in[0];
    const float* Wgc   = (const float*)d_in[1];
    const float* bgc   = (const float*)d_in[2];
    const float* Wres  = (const float*)d_in[3];
    const float* bres  = (const float*)d_in[4];
    const float* Wg    = (const float*)d_in[5];
    const float* bg    = (const float*)d_in[6];
    const float* w1    = (const float*)d_in[7];
    const float* b1    = (const float*)d_in[8];
    const float* w2    = (const float*)d_in[9];
    const float* b2    = (const float*)d_in[10];
    const float* gamma = (const float*)d_in[11];
    const float* beta  = (const float*)d_in[12];
    const int*   src   = (const int*)d_in[13];
    const int*   dst   = (const int*)d_in[14];
    float* out = (float*)d_out;

    k_zero<<<4096, 256>>>();
    k_deg<<<N_EDGES / 256, 256>>>(src, dst);
    k_rs<<<N_NODES / 256, 256>>>();
    k_scatter<<<N_EDGES / 8, 256>>>(feats, src, dst);      // 1 warp / edge
    k_xgemm<<<dim3(DIM / BN, N_NODES / BM), 256>>>(feats, Wgc, bgc, Wres, bres);
    k_gate<<<N_NODES / 8, 256>>>(Wg, bg);
    k_ffn1<<<dim3(HID / BN, CAP / BM, NEXP), 256>>>(w1, b1);
    k_ffn2<<<dim3(DIM / BN, CAP / BM, NEXP), 256>>>(w2, b2);
    k_combine<<<N_NODES / 128, 256>>>();
    k_bn<<<(N_NODES * DIM) / 256, 256>>>(gamma, beta, out);
}

// round 8
// speedup vs baseline: 1.9089x; 1.9089x over previous
#include <cuda_runtime.h>
#include <cuda_bf16.h>
#include <math.h>
#include <stdint.h>

#define N_NODES 16384
#define N_EDGES 262144
#define DIM 256          // D_IN == D == 256
#define HID 512
#define NEXP 64
#define CAP 1024
#define NSLOT (NEXP * CAP)   // 65536
#define BN_EPS 1e-5f

// ---------------- scratch (device globals; no allocation allowed) ----------------
__device__ int   g_deg_out[N_NODES];
__device__ int   g_deg_in[N_NODES];
__device__ float g_rs_out[N_NODES];
__device__ float g_rs_in[N_NODES];
__device__ float g_m[N_NODES * DIM];          // aggregated messages
__device__ float g_x[N_NODES * DIM];          // post-residual features
__device__ int   g_counts[NEXP];
__device__ int   g_tok[NSLOT];                // token id per expert slot
__device__ int   g_pair_slot[N_NODES * 2];
__device__ float g_pair_gate[N_NODES * 2];
__device__ float g_h1[(size_t)NSLOT * HID];   // expert hidden
__device__ float g_h2[(size_t)NSLOT * DIM];   // expert out
__device__ float g_y[N_NODES * DIM];          // pre-BN
__device__ float g_colsum[DIM];
__device__ float g_colsumsq[DIM];

// prepped (transposed + hi/lo split) weights, [n][k] bf16
__device__ __nv_bfloat16 pw1h[(size_t)NEXP * HID * DIM];  // [e][h][d]
__device__ __nv_bfloat16 pw1l[(size_t)NEXP * HID * DIM];
__device__ __nv_bfloat16 pw2h[(size_t)NEXP * DIM * HID];  // [e][d][h]
__device__ __nv_bfloat16 pw2l[(size_t)NEXP * DIM * HID];
__device__ __nv_bfloat16 pgch[DIM * DIM];                 // [n][k]
__device__ __nv_bfloat16 pgcl[DIM * DIM];
__device__ __nv_bfloat16 presh[DIM * DIM];
__device__ __nv_bfloat16 presl[DIM * DIM];

// ---------------- helpers ----------------
__device__ __forceinline__ void splitf(float v, __nv_bfloat16& h, __nv_bfloat16& l) {
    h = __float2bfloat16(v);
    l = __float2bfloat16(v - __bfloat162float(h));
}
__device__ __forceinline__ unsigned pack2(__nv_bfloat16 a, __nv_bfloat16 b) {
    __nv_bfloat162 p = __halves2bfloat162(a, b);   // .x -> low 16 bits (element k)
    return *reinterpret_cast<unsigned*>(&p);
}

__device__ __forceinline__ void mma_bf16(float* d, const unsigned* a, const unsigned* b) {
    asm volatile(
        "mma.sync.aligned.m16n8k16.row.col.f32.bf16.bf16.f32 "
        "{%0,%1,%2,%3}, {%4,%5,%6,%7}, {%8,%9}, {%0,%1,%2,%3};"
        : "+f"(d[0]), "+f"(d[1]), "+f"(d[2]), "+f"(d[3])
        : "r"(a[0]), "r"(a[1]), "r"(a[2]), "r"(a[3]), "r"(b[0]), "r"(b[1]));
}

// 128x128x32 tile step, bf16x3 error-compensated.
// A*: [128][20] uint32, each = bf16x2 k-pair (row-major M x Kpairs, stride 20 words -> conflict-free)
// B*: [128][20] uint32, rows = N, k-pairs (i.e., B stored transposed [n][k])
__device__ __forceinline__ void tile_mma3(
    const unsigned (*Ah)[20], const unsigned (*Al)[20],
    const unsigned (*Bh)[20], const unsigned (*Bl)[20],
    float (*acc)[8][4], int lane, int wm, int wn) {
    int g = lane >> 2, c = lane & 3;
#pragma unroll
    for (int ks = 0; ks < 2; ks++) {          // two k16 steps per 32-chunk
        int kp = ks * 8;
        unsigned ah[2][4], al[2][4];
#pragma unroll
        for (int mi = 0; mi < 2; mi++) {
            int rb = wm * 32 + mi * 16;
            ah[mi][0] = Ah[rb + g][kp + c];
            ah[mi][1] = Ah[rb + g + 8][kp + c];
            ah[mi][2] = Ah[rb + g][kp + c + 4];
            ah[mi][3] = Ah[rb + g + 8][kp + c + 4];
            al[mi][0] = Al[rb + g][kp + c];
            al[mi][1] = Al[rb + g + 8][kp + c];
            al[mi][2] = Al[rb + g][kp + c + 4];
            al[mi][3] = Al[rb + g + 8][kp + c + 4];
        }
#pragma unroll
        for (int ni = 0; ni < 8; ni++) {
            int nb = wn * 64 + ni * 8 + g;
            unsigned bh[2] = { Bh[nb][kp + c], Bh[nb][kp + c + 4] };
            unsigned bl[2] = { Bl[nb][kp + c], Bl[nb][kp + c + 4] };
#pragma unroll
            for (int mi = 0; mi < 2; mi++) {
                mma_bf16(acc[mi][ni], ah[mi], bh);
                mma_bf16(acc[mi][ni], ah[mi], bl);
                mma_bf16(acc[mi][ni], al[mi], bh);
            }
        }
    }
}

// load a 128x32 B tile (prepped bf16 [n][k] hi/lo) into smem; 256 threads
__device__ __forceinline__ void load_Btile(
    const __nv_bfloat16* __restrict__ ph, const __nv_bfloat16* __restrict__ pl,
    int col0, int kb, int Ktot, unsigned (*Bh)[20], unsigned (*Bl)[20], int tid) {
#pragma unroll
    for (int i = 0; i < 2; i++) {
        int lin = tid + i * 256;              // 0..511
        int n = lin >> 2, seg = lin & 3;      // 8 bf16 per seg
        size_t off = (size_t)(col0 + n) * Ktot + kb + seg * 8;
        *(uint4*)&Bh[n][seg * 4] = *(const uint4*)&ph[off];
        *(uint4*)&Bl[n][seg * 4] = *(const uint4*)&pl[off];
    }
}

// ---------------- zero everything that is accumulated ----------------
__global__ void k_zero() {
    int idx = blockIdx.x * blockDim.x + threadIdx.x;
    int stride = gridDim.x * blockDim.x;
    for (int i = idx; i < N_NODES * DIM; i += stride) g_m[i] = 0.f;
    if (idx < N_NODES) { g_deg_out[idx] = 0; g_deg_in[idx] = 0; }
    if (idx < NEXP) g_counts[idx] = 0;
    if (idx < DIM) { g_colsum[idx] = 0.f; g_colsumsq[idx] = 0.f; }
}

// ---------------- weight prep: transpose + hi/lo split ----------------
// W: slab-major [z][R][C] fp32  ->  out[z][C][R] bf16 hi/lo
__global__ void k_prep(const float* __restrict__ W, __nv_bfloat16* __restrict__ oh,
                       __nv_bfloat16* __restrict__ ol, int R, int C) {
    __shared__ float t[32][33];
    size_t slab = (size_t)blockIdx.z * R * C;
    int c0 = blockIdx.x * 32, r0 = blockIdx.y * 32;
    int tx = threadIdx.x, ty = threadIdx.y;    // 32 x 8
#pragma unroll
    for (int i = 0; i < 32; i += 8)
        t[ty + i][tx] = W[slab + (size_t)(r0 + ty + i) * C + c0 + tx];
    __syncthreads();
#pragma unroll
    for (int i = 0; i < 32; i += 8) {
        float v = t[tx][ty + i];
        __nv_bfloat16 h, l; splitf(v, h, l);
        size_t o = slab + (size_t)(c0 + ty + i) * R + r0 + tx;
        oh[o] = h; ol[o] = l;
    }
}

// ---------------- degree counts ----------------
__global__ void k_deg(const int* __restrict__ src, const int* __restrict__ dst) {
    int e = blockIdx.x * blockDim.x + threadIdx.x;
    if (e < N_EDGES) {
        atomicAdd(&g_deg_out[src[e]], 1);
        atomicAdd(&g_deg_in[dst[e]], 1);
    }
}

__global__ void k_rs() {
    int i = blockIdx.x * blockDim.x + threadIdx.x;
    if (i < N_NODES) {
        g_rs_out[i] = rsqrtf((float)max(g_deg_out[i], 1));
        g_rs_in[i]  = rsqrtf((float)max(g_deg_in[i], 1));
    }
}

// ---------------- edge scatter: m[dst] += feats[src] * rs_out[src] ----------------
__global__ void k_scatter(const float* __restrict__ feats,
                          const int* __restrict__ src, const int* __restrict__ dst) {
    int warp = (blockIdx.x * blockDim.x + threadIdx.x) >> 5;
    int lane = threadIdx.x & 31;
    if (warp >= N_EDGES) return;
    int s = src[warp], d = dst[warp];
    float sc = g_rs_out[s];
    const float4* fr = (const float4*)(feats + (size_t)s * DIM);
    float* mr = g_m + (size_t)d * DIM;
#pragma unroll
    for (int i = 0; i < 2; i++) {
        int j = lane + i * 32;           // 64 float4 per row
        float4 v = __ldg(&fr[j]);
        v.x *= sc; v.y *= sc; v.z *= sc; v.w *= sc;
        asm volatile("red.global.add.v4.f32 [%0], {%1,%2,%3,%4};"
                     :: "l"(mr + j * 4), "f"(v.x), "f"(v.y), "f"(v.z), "f"(v.w)
                     : "memory");
    }
}

// ---------------- x = (m*rs_in)@Wgc + feats@Wres + bgc + bres  (bf16x3, K=512) ----------------
__global__ __launch_bounds__(256) void k_xgemm(
    const float* __restrict__ feats,
    const float* __restrict__ bgc, const float* __restrict__ bres) {
    __shared__ unsigned Ah[128][20], Al[128][20], Bh[128][20], Bl[128][20];
    int tid = threadIdx.x, lane = tid & 31, wid = tid >> 5;
    int wm = wid & 3, wn = wid >> 2;
    int row0 = blockIdx.y * 128, col0 = blockIdx.x * 128;
    float acc[2][8][4] = {};

    for (int kb = 0; kb < 2 * DIM; kb += 32) {
        const float* A; const __nv_bfloat16 *ph, *pl; int kbase; bool scaled;
        if (kb < DIM) { A = g_m;   ph = pgch;  pl = pgcl;  kbase = kb;       scaled = true;  }
        else          { A = feats; ph = presh; pl = presl; kbase = kb - DIM; scaled = false; }
#pragma unroll
        for (int i = 0; i < 4; i++) {
            int lin = tid + i * 256;
            int r = lin >> 3, kq = lin & 7;           // kq = float4 index (2 k-pairs)
            float4 v = *(const float4*)&A[(size_t)(row0 + r) * DIM + kbase + kq * 4];
            if (scaled) { float s = g_rs_in[row0 + r]; v.x *= s; v.y *= s; v.z *= s; v.w *= s; }
            __nv_bfloat16 h0,l0,h1,l1,h2,l2,h3,l3;
            splitf(v.x,h0,l0); splitf(v.y,h1,l1); splitf(v.z,h2,l2); splitf(v.w,h3,l3);
            Ah[r][kq*2]   = pack2(h0,h1); Al[r][kq*2]   = pack2(l0,l1);
            Ah[r][kq*2+1] = pack2(h2,h3); Al[r][kq*2+1] = pack2(l2,l3);
        }
        load_Btile(ph, pl, col0, kbase, DIM, Bh, Bl, tid);
        __syncthreads();
        tile_mma3(Ah, Al, Bh, Bl, acc, lane, wm, wn);
        __syncthreads();
    }
    int g = lane >> 2, c2 = (lane & 3) * 2;
#pragma unroll
    for (int mi = 0; mi < 2; mi++) {
        int r = row0 + wm * 32 + mi * 16 + g;
#pragma unroll
        for (int ni = 0; ni < 8; ni++) {
            int col = col0 + wn * 64 + ni * 8 + c2;
            float b0 = bgc[col] + bres[col], b1 = bgc[col + 1] + bres[col + 1];
            *(float2*)&g_x[(size_t)r * DIM + col] =
                make_float2(acc[mi][ni][0] + b0, acc[mi][ni][1] + b1);
            *(float2*)&g_x[(size_t)(r + 8) * DIM + col] =
                make_float2(acc[mi][ni][2] + b0, acc[mi][ni][3] + b1);
        }
    }
}

// ---------------- gating: warp per token, top-2 + softmax, slot assignment ----------------
__global__ void k_gate(const float* __restrict__ Wg, const float* __restrict__ bg) {
    int t = (blockIdx.x * blockDim.x + threadIdx.x) >> 5;
    int lane = threadIdx.x & 31;
    if (t >= N_NODES) return;
    const float* xr = g_x + (size_t)t * DIM;
    float la = bg[lane], lb = bg[lane + 32];
    for (int k = 0; k < DIM; k++) {
        float xv = xr[k];
        la = fmaf(xv, Wg[k * NEXP + lane], la);
        lb = fmaf(xv, Wg[k * NEXP + lane + 32], lb);
    }
    float bv = la; int bi = lane;
    if (lb > bv) { bv = lb; bi = lane + 32; }
#pragma unroll
    for (int off = 16; off; off >>= 1) {
        float ov = __shfl_xor_sync(0xffffffffu, bv, off);
        int   oi = __shfl_xor_sync(0xffffffffu, bi, off);
        if (ov > bv || (ov == bv && oi < bi)) { bv = ov; bi = oi; }
    }
    float v0 = bv; int e0 = bi;
    float ca = (lane == e0) ? -INFINITY : la;
    float cb = (lane + 32 == e0) ? -INFINITY : lb;
    float bv2 = ca; int bi2 = lane;
    if (cb > bv2) { bv2 = cb; bi2 = lane + 32; }
#pragma unroll
    for (int off = 16; off; off >>= 1) {
        float ov = __shfl_xor_sync(0xffffffffu, bv2, off);
        int   oi = __shfl_xor_sync(0xffffffffu, bi2, off);
        if (ov > bv2 || (ov == bv2 && oi < bi2)) { bv2 = ov; bi2 = oi; }
    }
    float v1 = bv2; int e1 = bi2;
    if (lane == 0) {
        float g0 = 1.f / (1.f + expf(v1 - v0));
        float g1 = 1.f - g0;
        int r0 = atomicAdd(&g_counts[e0], 1);
        int s0 = (r0 < CAP) ? e0 * CAP + r0 : -1;
        if (s0 >= 0) g_tok[s0] = t;
        g_pair_slot[2 * t] = s0; g_pair_gate[2 * t] = g0;
        int r1 = atomicAdd(&g_counts[e1], 1);
        int s1 = (r1 < CAP) ? e1 * CAP + r1 : -1;
        if (s1 >= 0) g_tok[s1] = t;
        g_pair_slot[2 * t + 1] = s1; g_pair_gate[2 * t + 1] = g1;
    }
}

// ---------------- FFN1: h1 = gelu(gather(x) @ w1[e] + b1[e])  (bf16x3) ----------------
__global__ __launch_bounds__(256) void k_ffn1(const float* __restrict__ b1) {
    int e = blockIdx.z;
    int cnt = min(g_counts[e], CAP);
    int row0 = blockIdx.y * 128;
    if (row0 >= cnt) return;
    int col0 = blockIdx.x * 128;
    const __nv_bfloat16* ph = pw1h + (size_t)e * HID * DIM;   // [h][d]
    const __nv_bfloat16* pl = pw1l + (size_t)e * HID * DIM;
    __shared__ unsigned Ah[128][20], Al[128][20], Bh[128][20], Bl[128][20];
    __shared__ int stok[128];
    int tid = threadIdx.x, lane = tid & 31, wid = tid >> 5;
    int wm = wid & 3, wn = wid >> 2;
    if (tid < 128) {
        int rr = row0 + tid;
        stok[tid] = (rr < cnt) ? g_tok[e * CAP + rr] : 0;
    }
    __syncthreads();
    float acc[2][8][4] = {};

    for (int kb = 0; kb < DIM; kb += 32) {
#pragma unroll
        for (int i = 0; i < 4; i++) {
            int lin = tid + i * 256;
            int r = lin >> 3, kq = lin & 7;
            float4 v = *(const float4*)&g_x[(size_t)stok[r] * DIM + kb + kq * 4];
            __nv_bfloat16 h0,l0,h1,l1,h2,l2,h3,l3;
            splitf(v.x,h0,l0); splitf(v.y,h1,l1); splitf(v.z,h2,l2); splitf(v.w,h3,l3);
            Ah[r][kq*2]   = pack2(h0,h1); Al[r][kq*2]   = pack2(l0,l1);
            Ah[r][kq*2+1] = pack2(h2,h3); Al[r][kq*2+1] = pack2(l2,l3);
        }
        load_Btile(ph, pl, col0, kb, DIM, Bh, Bl, tid);
        __syncthreads();
        tile_mma3(Ah, Al, Bh, Bl, acc, lane, wm, wn);
        __syncthreads();
    }
    int g = lane >> 2, c2 = (lane & 3) * 2;
#pragma unroll
    for (int mi = 0; mi < 2; mi++) {
        int rl = wm * 32 + mi * 16 + g;
#pragma unroll
        for (int ni = 0; ni < 8; ni++) {
            int col = col0 + wn * 64 + ni * 8 + c2;
            float b0 = b1[e * HID + col], bb1 = b1[e * HID + col + 1];
#pragma unroll
            for (int h = 0; h < 2; h++) {
                int rr = row0 + rl + h * 8;
                if (rr < cnt) {
                    float v0 = acc[mi][ni][2 * h] + b0;
                    float v1 = acc[mi][ni][2 * h + 1] + bb1;
                    float o0 = 0.5f * v0 * (1.f + erff(v0 * 0.70710678118654752440f));
                    float o1 = 0.5f * v1 * (1.f + erff(v1 * 0.70710678118654752440f));
                    *(float2*)&g_h1[(size_t)(e * CAP + rr) * HID + col] = make_float2(o0, o1);
                }
            }
        }
    }
}

// ---------------- FFN2: h2 = h1 @ w2[e] + b2[e]  (bf16x3) ----------------
__global__ __launch_bounds__(256) void k_ffn2(const float* __restrict__ b2) {
    int e = blockIdx.z;
    int cnt = min(g_counts[e], CAP);
    int row0 = blockIdx.y * 128;
    if (row0 >= cnt) return;
    int col0 = blockIdx.x * 128;
    const __nv_bfloat16* ph = pw2h + (size_t)e * DIM * HID;   // [d][h]
    const __nv_bfloat16* pl = pw2l + (size_t)e * DIM * HID;
    __shared__ unsigned Ah[128][20], Al[128][20], Bh[128][20], Bl[128][20];
    int tid = threadIdx.x, lane = tid & 31, wid = tid >> 5;
    int wm = wid & 3, wn = wid >> 2;
    float acc[2][8][4] = {};

    for (int kb = 0; kb < HID; kb += 32) {
#pragma unroll
        for (int i = 0; i < 4; i++) {
            int lin = tid + i * 256;
            int r = lin >> 3, kq = lin & 7;
            float4 v = *(const float4*)&g_h1[(size_t)(e * CAP + row0 + r) * HID + kb + kq * 4];
            __nv_bfloat16 h0,l0,h1,l1,h2,l2,h3,l3;
            splitf(v.x,h0,l0); splitf(v.y,h1,l1); splitf(v.z,h2,l2); splitf(v.w,h3,l3);
            Ah[r][kq*2]   = pack2(h0,h1); Al[r][kq*2]   = pack2(l0,l1);
            Ah[r][kq*2+1] = pack2(h2,h3); Al[r][kq*2+1] = pack2(l2,l3);
        }
        load_Btile(ph, pl, col0, kb, HID, Bh, Bl, tid);
        __syncthreads();
        tile_mma3(Ah, Al, Bh, Bl, acc, lane, wm, wn);
        __syncthreads();
    }
    int g = lane >> 2, c2 = (lane & 3) * 2;
#pragma unroll
    for (int mi = 0; mi < 2; mi++) {
        int rl = wm * 32 + mi * 16 + g;
#pragma unroll
        for (int ni = 0; ni < 8; ni++) {
            int col = col0 + wn * 64 + ni * 8 + c2;
            float b0 = b2[e * DIM + col], bb1 = b2[e * DIM + col + 1];
#pragma unroll
            for (int h = 0; h < 2; h++) {
                int rr = row0 + rl + h * 8;
                if (rr < cnt) {
                    *(float2*)&g_h2[(size_t)(e * CAP + rr) * DIM + col] =
                        make_float2(acc[mi][ni][2 * h] + b0, acc[mi][ni][2 * h + 1] + bb1);
                }
            }
        }
    }
}

// ---------------- combine: y = x + g0*h2[s0] + g1*h2[s1]; column sums for BN ----------------
__global__ void k_combine() {
    int c = threadIdx.x;                 // 256 threads = 256 columns
    int t0 = blockIdx.x * 128;
    float sum = 0.f, sumsq = 0.f;
    for (int i = 0; i < 128; i++) {
        int t = t0 + i;
        int s0 = g_pair_slot[2 * t], s1 = g_pair_slot[2 * t + 1];
        float g0 = g_pair_gate[2 * t], g1 = g_pair_gate[2 * t + 1];
        float v = g_x[(size_t)t * DIM + c];
        if (s0 >= 0) v += g0 * g_h2[(size_t)s0 * DIM + c];
        if (s1 >= 0) v += g1 * g_h2[(size_t)s1 * DIM + c];
        g_y[(size_t)t * DIM + c] = v;
        sum += v; sumsq += v * v;
    }
    atomicAdd(&g_colsum[c], sum);
    atomicAdd(&g_colsumsq[c], sumsq);
}

// ---------------- batchnorm (train-mode, biased var) ----------------
__global__ void k_bn(const float* __restrict__ gamma, const float* __restrict__ beta,
                     float* __restrict__ out) {
    int idx = blockIdx.x * blockDim.x + threadIdx.x;
    if (idx >= N_NODES * DIM) return;
    int c = idx & (DIM - 1);
    const float invN = 1.f / (float)N_NODES;
    float mean = g_colsum[c] * invN;
    float var = g_colsumsq[c] * invN - mean * mean;
    out[idx] = (g_y[idx] - mean) * rsqrtf(var + BN_EPS) * gamma[c] + beta[c];
}

// ---------------- launcher ----------------
extern "C" void kernel_launch(void* const* d_in, const int* in_sizes, int n_in,
                              void* d_out, int out_size) {
    const float* feats = (const float*)d_in[0];
    const float* Wgc   = (const float*)d_in[1];
    const float* bgc   = (const float*)d_in[2];
    const float* Wres  = (const float*)d_in[3];
    const float* bres  = (const float*)d_in[4];
    const float* Wg    = (const float*)d_in[5];
    const float* bg    = (const float*)d_in[6];
    const float* w1    = (const float*)d_in[7];
    const float* b1    = (const float*)d_in[8];
    const float* w2    = (const float*)d_in[9];
    const float* b2    = (const float*)d_in[10];
    const float* gamma = (const float*)d_in[11];
    const float* beta  = (const float*)d_in[12];
    const int*   src   = (const int*)d_in[13];
    const int*   dst   = (const int*)d_in[14];
    float* out = (float*)d_out;

    __nv_bfloat16 *d_pw1h, *d_pw1l, *d_pw2h, *d_pw2l, *d_pgch, *d_pgcl, *d_presh, *d_presl;
    cudaGetSymbolAddress((void**)&d_pw1h, pw1h);
    cudaGetSymbolAddress((void**)&d_pw1l, pw1l);
    cudaGetSymbolAddress((void**)&d_pw2h, pw2h);
    cudaGetSymbolAddress((void**)&d_pw2l, pw2l);
    cudaGetSymbolAddress((void**)&d_pgch, pgch);
    cudaGetSymbolAddress((void**)&d_pgcl, pgcl);
    cudaGetSymbolAddress((void**)&d_presh, presh);
    cudaGetSymbolAddress((void**)&d_presl, presl);

    dim3 tb(32, 8);
    k_zero<<<4096, 256>>>();
    // weight prep (transpose + hi/lo split)
    k_prep<<<dim3(HID / 32, DIM / 32, NEXP), tb>>>(w1, d_pw1h, d_pw1l, DIM, HID);
    k_prep<<<dim3(DIM / 32, HID / 32, NEXP), tb>>>(w2, d_pw2h, d_pw2l, HID, DIM);
    k_prep<<<dim3(DIM / 32, DIM / 32, 1),    tb>>>(Wgc,  d_pgch,  d_pgcl,  DIM, DIM);
    k_prep<<<dim3(DIM / 32, DIM / 32, 1),    tb>>>(Wres, d_presh, d_presl, DIM, DIM);

    k_deg<<<N_EDGES / 256, 256>>>(src, dst);
    k_rs<<<N_NODES / 256, 256>>>();
    k_scatter<<<N_EDGES / 8, 256>>>(feats, src, dst);      // 1 warp / edge
    k_xgemm<<<dim3(DIM / 128, N_NODES / 128), 256>>>(feats, bgc, bres);
    k_gate<<<N_NODES / 8, 256>>>(Wg, bg);
    k_ffn1<<<dim3(HID / 128, CAP / 128, NEXP), 256>>>(b1);
    k_ffn2<<<dim3(DIM / 128, CAP / 128, NEXP), 256>>>(b2);
    k_combine<<<N_NODES / 128, 256>>>();
    k_bn<<<(N_NODES * DIM) / 256, 256>>>(gamma, beta, out);
}

// round 9
// speedup vs baseline: 2.1991x; 1.1520x over previous
#include <cuda_runtime.h>
#include <cuda_bf16.h>
#include <math.h>
#include <stdint.h>

#define N_NODES 16384
#define N_EDGES 262144
#define DIM 256          // D_IN == D == 256
#define HID 512
#define NEXP 64
#define CAP 1024
#define NSLOT (NEXP * CAP)   // 65536
#define BN_EPS 1e-5f

// ---------------- scratch (device globals; no allocation allowed) ----------------
__device__ int   g_deg_out[N_NODES];
__device__ int   g_deg_in[N_NODES];
__device__ float g_rs_out[N_NODES];
__device__ float g_rs_in[N_NODES];
__device__ float g_m[N_NODES * DIM];          // aggregated messages
__device__ float g_x[N_NODES * DIM];          // post-residual features (fp32, gate+combine)
__device__ int   g_counts[NEXP];
__device__ int   g_tok[NSLOT];                // token id per expert slot
__device__ int   g_pair_slot[N_NODES * 2];
__device__ float g_pair_gate[N_NODES * 2];
__device__ float g_h2[(size_t)NSLOT * DIM];   // expert out (fp32)
__device__ float g_y[N_NODES * DIM];          // pre-BN
__device__ float g_colsum[DIM];
__device__ float g_colsumsq[DIM];

// pre-split bf16 hi/lo activations (16B-aligned for cp.async)
__device__ __align__(16) __nv_bfloat16 g_axh[(size_t)N_NODES * 2 * DIM]; // [row][0:256]=m*rs, [256:512]=feats
__device__ __align__(16) __nv_bfloat16 g_axl[(size_t)N_NODES * 2 * DIM];
__device__ __align__(16) __nv_bfloat16 g_xh[(size_t)N_NODES * DIM];
__device__ __align__(16) __nv_bfloat16 g_xl[(size_t)N_NODES * DIM];
__device__ __align__(16) __nv_bfloat16 g_h1h[(size_t)NSLOT * HID];
__device__ __align__(16) __nv_bfloat16 g_h1l[(size_t)NSLOT * HID];

// prepped (transposed + hi/lo split) weights, [n][k] bf16
__device__ __align__(16) __nv_bfloat16 pw1h[(size_t)NEXP * HID * DIM];  // [e][h][d]
__device__ __align__(16) __nv_bfloat16 pw1l[(size_t)NEXP * HID * DIM];
__device__ __align__(16) __nv_bfloat16 pw2h[(size_t)NEXP * DIM * HID];  // [e][d][h]
__device__ __align__(16) __nv_bfloat16 pw2l[(size_t)NEXP * DIM * HID];
__device__ __align__(16) __nv_bfloat16 pgch[DIM * DIM];                 // [n][k]
__device__ __align__(16) __nv_bfloat16 pgcl[DIM * DIM];
__device__ __align__(16) __nv_bfloat16 presh[DIM * DIM];
__device__ __align__(16) __nv_bfloat16 presl[DIM * DIM];

// ---------------- helpers ----------------
__device__ __forceinline__ void splitf(float v, __nv_bfloat16& h, __nv_bfloat16& l) {
    h = __float2bfloat16(v);
    l = __float2bfloat16(v - __bfloat162float(h));
}
__device__ __forceinline__ unsigned pack2(__nv_bfloat16 a, __nv_bfloat16 b) {
    __nv_bfloat162 p = __halves2bfloat162(a, b);   // .x -> low 16 bits (element k)
    return *reinterpret_cast<unsigned*>(&p);
}

__device__ __forceinline__ void cp16(void* sdst, const void* gsrc) {
    unsigned d = (unsigned)__cvta_generic_to_shared(sdst);
    asm volatile("cp.async.cg.shared.global [%0], [%1], 16;" :: "r"(d), "l"(gsrc));
}
#define CP_COMMIT() asm volatile("cp.async.commit_group;")
#define CP_WAIT1()  asm volatile("cp.async.wait_group 1;")

__device__ __forceinline__ void mma_bf16(float* d, const unsigned* a, const unsigned* b) {
    asm volatile(
        "mma.sync.aligned.m16n8k16.row.col.f32.bf16.bf16.f32 "
        "{%0,%1,%2,%3}, {%4,%5,%6,%7}, {%8,%9}, {%0,%1,%2,%3};"
        : "+f"(d[0]), "+f"(d[1]), "+f"(d[2]), "+f"(d[3])
        : "r"(a[0]), "r"(a[1]), "r"(a[2]), "r"(a[3]), "r"(b[0]), "r"(b[1]));
}

// smem: two stages, each 4 arrays of [128][20] uint32 (stride 20 -> conflict-free frags)
#define ARR_W   2560        // 128*20 words
#define STAGE_W 10240       // 4 arrays
#define SMEM_BYTES (2 * STAGE_W * 4)

// 128x128x32 tile step, bf16x3 error-compensated
__device__ __forceinline__ void tile_mma3(
    const unsigned* __restrict__ sAh, const unsigned* __restrict__ sAl,
    const unsigned* __restrict__ sBh, const unsigned* __restrict__ sBl,
    float (*acc)[8][4], int lane, int wm, int wn) {
    const unsigned (*Ah)[20] = (const unsigned(*)[20])sAh;
    const unsigned (*Al)[20] = (const unsigned(*)[20])sAl;
    const unsigned (*Bh)[20] = (const unsigned(*)[20])sBh;
    const unsigned (*Bl)[20] = (const unsigned(*)[20])sBl;
    int g = lane >> 2, c = lane & 3;
#pragma unroll
    for (int ks = 0; ks < 2; ks++) {
        int kp = ks * 8;
        unsigned ah[2][4], al[2][4];
#pragma unroll
        for (int mi = 0; mi < 2; mi++) {
            int rb = wm * 32 + mi * 16;
            ah[mi][0] = Ah[rb + g][kp + c];
            ah[mi][1] = Ah[rb + g + 8][kp + c];
            ah[mi][2] = Ah[rb + g][kp + c + 4];
            ah[mi][3] = Ah[rb + g + 8][kp + c + 4];
            al[mi][0] = Al[rb + g][kp + c];
            al[mi][1] = Al[rb + g + 8][kp + c];
            al[mi][2] = Al[rb + g][kp + c + 4];
            al[mi][3] = Al[rb + g + 8][kp + c + 4];
        }
#pragma unroll
        for (int ni = 0; ni < 8; ni++) {
            int nb = wn * 64 + ni * 8 + g;
            unsigned bh[2] = { Bh[nb][kp + c], Bh[nb][kp + c + 4] };
            unsigned bl[2] = { Bl[nb][kp + c], Bl[nb][kp + c + 4] };
#pragma unroll
            for (int mi = 0; mi < 2; mi++) {
                mma_bf16(acc[mi][ni], ah[mi], bh);
                mma_bf16(acc[mi][ni], ah[mi], bl);
                mma_bf16(acc[mi][ni], al[mi], bh);
            }
        }
    }
}

// prefetch one 128x32 bf16 hi/lo operand tile via cp.async
// rows: optional smem row-index table (gather); else rbase+r
__device__ __forceinline__ void pref_tile(
    const __nv_bfloat16* __restrict__ ph, const __nv_bfloat16* __restrict__ pl,
    const int* rows, int rbase, int rstride, int kb,
    unsigned* sh, unsigned* sl, int tid) {
#pragma unroll
    for (int i = 0; i < 2; i++) {
        int lin = tid + i * 256;
        int r = lin >> 2, seg = lin & 3;
        int grow = rows ? rows[r] : (rbase + r);
        size_t off = (size_t)grow * rstride + kb + seg * 8;
        cp16(&sh[r * 20 + seg * 4], ph + off);
        cp16(&sl[r * 20 + seg * 4], pl + off);
    }
}

// ---------------- zero everything that is accumulated ----------------
__global__ void k_zero() {
    int idx = blockIdx.x * blockDim.x + threadIdx.x;
    int stride = gridDim.x * blockDim.x;
    for (int i = idx; i < N_NODES * DIM; i += stride) g_m[i] = 0.f;
    if (idx < N_NODES) { g_deg_out[idx] = 0; g_deg_in[idx] = 0; }
    if (idx < NEXP) g_counts[idx] = 0;
    if (idx < DIM) { g_colsum[idx] = 0.f; g_colsumsq[idx] = 0.f; }
}

// ---------------- weight prep: transpose + hi/lo split ----------------
// W: slab-major [z][R][C] fp32  ->  out[z][C][R] bf16 hi/lo
__global__ void k_prep(const float* __restrict__ W, __nv_bfloat16* __restrict__ oh,
                       __nv_bfloat16* __restrict__ ol, int R, int C) {
    __shared__ float t[32][33];
    size_t slab = (size_t)blockIdx.z * R * C;
    int c0 = blockIdx.x * 32, r0 = blockIdx.y * 32;
    int tx = threadIdx.x, ty = threadIdx.y;    // 32 x 8
#pragma unroll
    for (int i = 0; i < 32; i += 8)
        t[ty + i][tx] = W[slab + (size_t)(r0 + ty + i) * C + c0 + tx];
    __syncthreads();
#pragma unroll
    for (int i = 0; i < 32; i += 8) {
        float v = t[tx][ty + i];
        __nv_bfloat16 h, l; splitf(v, h, l);
        size_t o = slab + (size_t)(c0 + ty + i) * R + r0 + tx;
        oh[o] = h; ol[o] = l;
    }
}

// ---------------- activation pre-split for xgemm A: [row][0:256]=m*rs_in, [256:512]=feats ----------------
__global__ void k_prea(const float* __restrict__ feats) {
    int idx = blockIdx.x * blockDim.x + threadIdx.x;   // one per 4 elems
    int lin = idx * 4;
    if (lin >= N_NODES * 2 * DIM) return;
    int row = lin >> 9, c = lin & 511;
    float4 v;
    if (c < DIM) {
        v = *(const float4*)&g_m[(size_t)row * DIM + c];
        float s = g_rs_in[row];
        v.x *= s; v.y *= s; v.z *= s; v.w *= s;
    } else {
        v = *(const float4*)&feats[(size_t)row * DIM + (c - DIM)];
    }
    __nv_bfloat16 h0,l0,h1,l1,h2,l2,h3,l3;
    splitf(v.x,h0,l0); splitf(v.y,h1,l1); splitf(v.z,h2,l2); splitf(v.w,h3,l3);
    *(uint2*)&g_axh[lin] = make_uint2(pack2(h0,h1), pack2(h2,h3));
    *(uint2*)&g_axl[lin] = make_uint2(pack2(l0,l1), pack2(l2,l3));
}

// ---------------- degree counts ----------------
__global__ void k_deg(const int* __restrict__ src, const int* __restrict__ dst) {
    int e = blockIdx.x * blockDim.x + threadIdx.x;
    if (e < N_EDGES) {
        atomicAdd(&g_deg_out[src[e]], 1);
        atomicAdd(&g_deg_in[dst[e]], 1);
    }
}

__global__ void k_rs() {
    int i = blockIdx.x * blockDim.x + threadIdx.x;
    if (i < N_NODES) {
        g_rs_out[i] = rsqrtf((float)max(g_deg_out[i], 1));
        g_rs_in[i]  = rsqrtf((float)max(g_deg_in[i], 1));
    }
}

// ---------------- edge scatter: m[dst] += feats[src] * rs_out[src] ----------------
__global__ void k_scatter(const float* __restrict__ feats,
                          const int* __restrict__ src, const int* __restrict__ dst) {
    int warp = (blockIdx.x * blockDim.x + threadIdx.x) >> 5;
    int lane = threadIdx.x & 31;
    if (warp >= N_EDGES) return;
    int s = src[warp], d = dst[warp];
    float sc = g_rs_out[s];
    const float4* fr = (const float4*)(feats + (size_t)s * DIM);
    float* mr = g_m + (size_t)d * DIM;
#pragma unroll
    for (int i = 0; i < 2; i++) {
        int j = lane + i * 32;           // 64 float4 per row
        float4 v = __ldg(&fr[j]);
        v.x *= sc; v.y *= sc; v.z *= sc; v.w *= sc;
        asm volatile("red.global.add.v4.f32 [%0], {%1,%2,%3,%4};"
                     :: "l"(mr + j * 4), "f"(v.x), "f"(v.y), "f"(v.z), "f"(v.w)
                     : "memory");
    }
}

// ---------------- x = ax @ [Wgc;Wres] + bgc + bres  (bf16x3 pipelined, K=512) ----------------
__global__ __launch_bounds__(256) void k_xgemm(
    const float* __restrict__ bgc, const float* __restrict__ bres) {
    extern __shared__ unsigned sm[];
    int tid = threadIdx.x, lane = tid & 31, wid = tid >> 5;
    int wm = wid & 3, wn = wid >> 2;
    int row0 = blockIdx.y * 128, col0 = blockIdx.x * 128;
    float acc[2][8][4] = {};
    const int NCH = 2 * DIM / 32;   // 16

    // prefetch chunk 0
    {
        unsigned* s0 = sm;
        pref_tile(g_axh, g_axl, nullptr, row0, 2 * DIM, 0, s0, s0 + ARR_W, tid);
        pref_tile(pgch, pgcl, nullptr, col0, DIM, 0, s0 + 2 * ARR_W, s0 + 3 * ARR_W, tid);
    }
    CP_COMMIT();

    for (int ch = 0; ch < NCH; ch++) {
        int cur = ch & 1;
        if (ch + 1 < NCH) {
            unsigned* s = sm + (cur ^ 1) * STAGE_W;
            int kb = (ch + 1) * 32;
            pref_tile(g_axh, g_axl, nullptr, row0, 2 * DIM, kb, s, s + ARR_W, tid);
            if (kb < DIM)
                pref_tile(pgch, pgcl, nullptr, col0, DIM, kb, s + 2 * ARR_W, s + 3 * ARR_W, tid);
            else
                pref_tile(presh, presl, nullptr, col0, DIM, kb - DIM, s + 2 * ARR_W, s + 3 * ARR_W, tid);
        }
        CP_COMMIT();
        CP_WAIT1();
        __syncthreads();
        unsigned* s = sm + cur * STAGE_W;
        tile_mma3(s, s + ARR_W, s + 2 * ARR_W, s + 3 * ARR_W, acc, lane, wm, wn);
        __syncthreads();
    }

    int g = lane >> 2, c2 = (lane & 3) * 2;
#pragma unroll
    for (int mi = 0; mi < 2; mi++) {
        int r = row0 + wm * 32 + mi * 16 + g;
#pragma unroll
        for (int ni = 0; ni < 8; ni++) {
            int col = col0 + wn * 64 + ni * 8 + c2;
            float b0 = bgc[col] + bres[col], b1 = bgc[col + 1] + bres[col + 1];
            float v00 = acc[mi][ni][0] + b0, v01 = acc[mi][ni][1] + b1;
            float v10 = acc[mi][ni][2] + b0, v11 = acc[mi][ni][3] + b1;
            *(float2*)&g_x[(size_t)r * DIM + col] = make_float2(v00, v01);
            *(float2*)&g_x[(size_t)(r + 8) * DIM + col] = make_float2(v10, v11);
            __nv_bfloat16 h0,l0,h1,l1;
            splitf(v00,h0,l0); splitf(v01,h1,l1);
            *(unsigned*)&g_xh[(size_t)r * DIM + col] = pack2(h0,h1);
            *(unsigned*)&g_xl[(size_t)r * DIM + col] = pack2(l0,l1);
            splitf(v10,h0,l0); splitf(v11,h1,l1);
            *(unsigned*)&g_xh[(size_t)(r + 8) * DIM + col] = pack2(h0,h1);
            *(unsigned*)&g_xl[(size_t)(r + 8) * DIM + col] = pack2(l0,l1);
        }
    }
}

// ---------------- gating: warp per token, top-2 + softmax, slot assignment ----------------
__global__ void k_gate(const float* __restrict__ Wg, const float* __restrict__ bg) {
    int t = (blockIdx.x * blockDim.x + threadIdx.x) >> 5;
    int lane = threadIdx.x & 31;
    if (t >= N_NODES) return;
    const float* xr = g_x + (size_t)t * DIM;
    float la = bg[lane], lb = bg[lane + 32];
    for (int k = 0; k < DIM; k++) {
        float xv = xr[k];
        la = fmaf(xv, Wg[k * NEXP + lane], la);
        lb = fmaf(xv, Wg[k * NEXP + lane + 32], lb);
    }
    float bv = la; int bi = lane;
    if (lb > bv) { bv = lb; bi = lane + 32; }
#pragma unroll
    for (int off = 16; off; off >>= 1) {
        float ov = __shfl_xor_sync(0xffffffffu, bv, off);
        int   oi = __shfl_xor_sync(0xffffffffu, bi, off);
        if (ov > bv || (ov == bv && oi < bi)) { bv = ov; bi = oi; }
    }
    float v0 = bv; int e0 = bi;
    float ca = (lane == e0) ? -INFINITY : la;
    float cb = (lane + 32 == e0) ? -INFINITY : lb;
    float bv2 = ca; int bi2 = lane;
    if (cb > bv2) { bv2 = cb; bi2 = lane + 32; }
#pragma unroll
    for (int off = 16; off; off >>= 1) {
        float ov = __shfl_xor_sync(0xffffffffu, bv2, off);
        int   oi = __shfl_xor_sync(0xffffffffu, bi2, off);
        if (ov > bv2 || (ov == bv2 && oi < bi2)) { bv2 = ov; bi2 = oi; }
    }
    float v1 = bv2; int e1 = bi2;
    if (lane == 0) {
        float g0 = 1.f / (1.f + expf(v1 - v0));
        float g1 = 1.f - g0;
        int r0 = atomicAdd(&g_counts[e0], 1);
        int s0 = (r0 < CAP) ? e0 * CAP + r0 : -1;
        if (s0 >= 0) g_tok[s0] = t;
        g_pair_slot[2 * t] = s0; g_pair_gate[2 * t] = g0;
        int r1 = atomicAdd(&g_counts[e1], 1);
        int s1 = (r1 < CAP) ? e1 * CAP + r1 : -1;
        if (s1 >= 0) g_tok[s1] = t;
        g_pair_slot[2 * t + 1] = s1; g_pair_gate[2 * t + 1] = g1;
    }
}

// ---------------- FFN1: h1 = gelu(gather(x) @ w1[e] + b1[e])  (bf16x3 pipelined) ----------------
__global__ __launch_bounds__(256) void k_ffn1(const float* __restrict__ b1) {
    int e = blockIdx.z;
    int cnt = min(g_counts[e], CAP);
    int row0 = blockIdx.y * 128;
    if (row0 >= cnt) return;
    int col0 = blockIdx.x * 128;
    const __nv_bfloat16* ph = pw1h + (size_t)e * HID * DIM;   // [h][d]
    const __nv_bfloat16* pl = pw1l + (size_t)e * HID * DIM;
    extern __shared__ unsigned sm[];
    __shared__ int stok[128];
    int tid = threadIdx.x, lane = tid & 31, wid = tid >> 5;
    int wm = wid & 3, wn = wid >> 2;
    if (tid < 128) {
        int rr = row0 + tid;
        stok[tid] = (rr < cnt) ? g_tok[e * CAP + rr] : 0;
    }
    __syncthreads();
    float acc[2][8][4] = {};
    const int NCH = DIM / 32;   // 8

    {
        unsigned* s0 = sm;
        pref_tile(g_xh, g_xl, stok, 0, DIM, 0, s0, s0 + ARR_W, tid);
        pref_tile(ph, pl, nullptr, col0, DIM, 0, s0 + 2 * ARR_W, s0 + 3 * ARR_W, tid);
    }
    CP_COMMIT();

    for (int ch = 0; ch < NCH; ch++) {
        int cur = ch & 1;
        if (ch + 1 < NCH) {
            unsigned* s = sm + (cur ^ 1) * STAGE_W;
            int kb = (ch + 1) * 32;
            pref_tile(g_xh, g_xl, stok, 0, DIM, kb, s, s + ARR_W, tid);
            pref_tile(ph, pl, nullptr, col0, DIM, kb, s + 2 * ARR_W, s + 3 * ARR_W, tid);
        }
        CP_COMMIT();
        CP_WAIT1();
        __syncthreads();
        unsigned* s = sm + cur * STAGE_W;
        tile_mma3(s, s + ARR_W, s + 2 * ARR_W, s + 3 * ARR_W, acc, lane, wm, wn);
        __syncthreads();
    }

    int g = lane >> 2, c2 = (lane & 3) * 2;
#pragma unroll
    for (int mi = 0; mi < 2; mi++) {
        int rl = wm * 32 + mi * 16 + g;
#pragma unroll
        for (int ni = 0; ni < 8; ni++) {
            int col = col0 + wn * 64 + ni * 8 + c2;
            float b0 = b1[e * HID + col], bb1 = b1[e * HID + col + 1];
#pragma unroll
            for (int h = 0; h < 2; h++) {
                int rr = row0 + rl + h * 8;
                if (rr < cnt) {
                    float v0 = acc[mi][ni][2 * h] + b0;
                    float v1 = acc[mi][ni][2 * h + 1] + bb1;
                    float o0 = 0.5f * v0 * (1.f + erff(v0 * 0.70710678118654752440f));
                    float o1 = 0.5f * v1 * (1.f + erff(v1 * 0.70710678118654752440f));
                    __nv_bfloat16 hh0,ll0,hh1,ll1;
                    splitf(o0,hh0,ll0); splitf(o1,hh1,ll1);
                    size_t off = (size_t)(e * CAP + rr) * HID + col;
                    *(unsigned*)&g_h1h[off] = pack2(hh0,hh1);
                    *(unsigned*)&g_h1l[off] = pack2(ll0,ll1);
                }
            }
        }
    }
}

// ---------------- FFN2: h2 = h1 @ w2[e] + b2[e]  (bf16x3 pipelined) ----------------
__global__ __launch_bounds__(256) void k_ffn2(const float* __restrict__ b2) {
    int e = blockIdx.z;
    int cnt = min(g_counts[e], CAP);
    int row0 = blockIdx.y * 128;
    if (row0 >= cnt) return;
    int col0 = blockIdx.x * 128;
    const __nv_bfloat16* ph = pw2h + (size_t)e * DIM * HID;   // [d][h]
    const __nv_bfloat16* pl = pw2l + (size_t)e * DIM * HID;
    extern __shared__ unsigned sm[];
    int tid = threadIdx.x, lane = tid & 31, wid = tid >> 5;
    int wm = wid & 3, wn = wid >> 2;
    int abase = e * CAP + row0;
    float acc[2][8][4] = {};
    const int NCH = HID / 32;   // 16

    {
        unsigned* s0 = sm;
        pref_tile(g_h1h, g_h1l, nullptr, abase, HID, 0, s0, s0 + ARR_W, tid);
        pref_tile(ph, pl, nullptr, col0, HID, 0, s0 + 2 * ARR_W, s0 + 3 * ARR_W, tid);
    }
    CP_COMMIT();

    for (int ch = 0; ch < NCH; ch++) {
        int cur = ch & 1;
        if (ch + 1 < NCH) {
            unsigned* s = sm + (cur ^ 1) * STAGE_W;
            int kb = (ch + 1) * 32;
            pref_tile(g_h1h, g_h1l, nullptr, abase, HID, kb, s, s + ARR_W, tid);
            pref_tile(ph, pl, nullptr, col0, HID, kb, s + 2 * ARR_W, s + 3 * ARR_W, tid);
        }
        CP_COMMIT();
        CP_WAIT1();
        __syncthreads();
        unsigned* s = sm + cur * STAGE_W;
        tile_mma3(s, s + ARR_W, s + 2 * ARR_W, s + 3 * ARR_W, acc, lane, wm, wn);
        __syncthreads();
    }

    int g = lane >> 2, c2 = (lane & 3) * 2;
#pragma unroll
    for (int mi = 0; mi < 2; mi++) {
        int rl = wm * 32 + mi * 16 + g;
#pragma unroll
        for (int ni = 0; ni < 8; ni++) {
            int col = col0 + wn * 64 + ni * 8 + c2;
            float b0 = b2[e * DIM + col], bb1 = b2[e * DIM + col + 1];
#pragma unroll
            for (int h = 0; h < 2; h++) {
                int rr = row0 + rl + h * 8;
                if (rr < cnt) {
                    *(float2*)&g_h2[(size_t)(e * CAP + rr) * DIM + col] =
                        make_float2(acc[mi][ni][2 * h] + b0, acc[mi][ni][2 * h + 1] + bb1);
                }
            }
        }
    }
}

// ---------------- combine: y = x + g0*h2[s0] + g1*h2[s1]; column sums for BN ----------------
__global__ void k_combine() {
    int c = threadIdx.x;                 // 256 threads = 256 columns
    int t0 = blockIdx.x * 128;
    float sum = 0.f, sumsq = 0.f;
    for (int i = 0; i < 128; i++) {
        int t = t0 + i;
        int s0 = g_pair_slot[2 * t], s1 = g_pair_slot[2 * t + 1];
        float g0 = g_pair_gate[2 * t], g1 = g_pair_gate[2 * t + 1];
        float v = g_x[(size_t)t * DIM + c];
        if (s0 >= 0) v += g0 * g_h2[(size_t)s0 * DIM + c];
        if (s1 >= 0) v += g1 * g_h2[(size_t)s1 * DIM + c];
        g_y[(size_t)t * DIM + c] = v;
        sum += v; sumsq += v * v;
    }
    atomicAdd(&g_colsum[c], sum);
    atomicAdd(&g_colsumsq[c], sumsq);
}

// ---------------- batchnorm (train-mode, biased var) ----------------
__global__ void k_bn(const float* __restrict__ gamma, const float* __restrict__ beta,
                     float* __restrict__ out) {
    int idx = blockIdx.x * blockDim.x + threadIdx.x;
    if (idx >= N_NODES * DIM) return;
    int c = idx & (DIM - 1);
    const float invN = 1.f / (float)N_NODES;
    float mean = g_colsum[c] * invN;
    float var = g_colsumsq[c] * invN - mean * mean;
    out[idx] = (g_y[idx] - mean) * rsqrtf(var + BN_EPS) * gamma[c] + beta[c];
}

// ---------------- launcher ----------------
extern "C" void kernel_launch(void* const* d_in, const int* in_sizes, int n_in,
                              void* d_out, int out_size) {
    const float* feats = (const float*)d_in[0];
    const float* Wgc   = (const float*)d_in[1];
    const float* bgc   = (const float*)d_in[2];
    const float* Wres  = (const float*)d_in[3];
    const float* bres  = (const float*)d_in[4];
    const float* Wg    = (const float*)d_in[5];
    const float* bg    = (const float*)d_in[6];
    const float* w1    = (const float*)d_in[7];
    const float* b1    = (const float*)d_in[8];
    const float* w2    = (const float*)d_in[9];
    const float* b2    = (const float*)d_in[10];
    const float* gamma = (const float*)d_in[11];
    const float* beta  = (const float*)d_in[12];
    const int*   src   = (const int*)d_in[13];
    const int*   dst   = (const int*)d_in[14];
    float* out = (float*)d_out;

    __nv_bfloat16 *d_pw1h, *d_pw1l, *d_pw2h, *d_pw2l, *d_pgch, *d_pgcl, *d_presh, *d_presl;
    cudaGetSymbolAddress((void**)&d_pw1h, pw1h);
    cudaGetSymbolAddress((void**)&d_pw1l, pw1l);
    cudaGetSymbolAddress((void**)&d_pw2h, pw2h);
    cudaGetSymbolAddress((void**)&d_pw2l, pw2l);
    cudaGetSymbolAddress((void**)&d_pgch, pgch);
    cudaGetSymbolAddress((void**)&d_pgcl, pgcl);
    cudaGetSymbolAddress((void**)&d_presh, presh);
    cudaGetSymbolAddress((void**)&d_presl, presl);

    cudaFuncSetAttribute(k_xgemm, cudaFuncAttributeMaxDynamicSharedMemorySize, SMEM_BYTES);
    cudaFuncSetAttribute(k_ffn1,  cudaFuncAttributeMaxDynamicSharedMemorySize, SMEM_BYTES);
    cudaFuncSetAttribute(k_ffn2,  cudaFuncAttributeMaxDynamicSharedMemorySize, SMEM_BYTES);

    dim3 tb(32, 8);
    k_zero<<<4096, 256>>>();
    // weight prep (transpose + hi/lo split)
    k_prep<<<dim3(HID / 32, DIM / 32, NEXP), tb>>>(w1, d_pw1h, d_pw1l, DIM, HID);
    k_prep<<<dim3(DIM / 32, HID / 32, NEXP), tb>>>(w2, d_pw2h, d_pw2l, HID, DIM);
    k_prep<<<dim3(DIM / 32, DIM / 32, 1),    tb>>>(Wgc,  d_pgch,  d_pgcl,  DIM, DIM);
    k_prep<<<dim3(DIM / 32, DIM / 32, 1),    tb>>>(Wres, d_presh, d_presl, DIM, DIM);

    k_deg<<<N_EDGES / 256, 256>>>(src, dst);
    k_rs<<<N_NODES / 256, 256>>>();
    k_scatter<<<N_EDGES / 8, 256>>>(feats, src, dst);      // 1 warp / edge
    k_prea<<<(N_NODES * 2 * DIM / 4 + 255) / 256, 256>>>(feats);
    k_xgemm<<<dim3(DIM / 128, N_NODES / 128), 256, SMEM_BYTES>>>(bgc, bres);
    k_gate<<<N_NODES / 8, 256>>>(Wg, bg);
    k_ffn1<<<dim3(HID / 128, CAP / 128, NEXP), 256, SMEM_BYTES>>>(b1);
    k_ffn2<<<dim3(DIM / 128, CAP / 128, NEXP), 256, SMEM_BYTES>>>(b2);
    k_combine<<<N_NODES / 128, 256>>>();
    k_bn<<<(N_NODES * DIM) / 256, 256>>>(gamma, beta, out);
}

// round 13
// speedup vs baseline: 2.2146x; 1.0070x over previous
#include <cuda_runtime.h>
#include <cuda_bf16.h>
#include <math.h>
#include <stdint.h>

#define N_NODES 16384
#define N_EDGES 262144
#define DIM 256          // D_IN == D == 256
#define HID 512
#define NEXP 64
#define CAP 1024
#define NSLOT (NEXP * CAP)   // 65536
#define BN_EPS 1e-5f

// ---------------- scratch (device globals; no allocation allowed) ----------------
__device__ int   g_deg_out[N_NODES];
__device__ int   g_deg_in[N_NODES];
__device__ float g_rs_out[N_NODES];
__device__ float g_rs_in[N_NODES];
__device__ float g_m[N_NODES * DIM];          // aggregated messages
__device__ float g_x[N_NODES * DIM];          // post-residual features (fp32, gate+combine)
__device__ int   g_counts[NEXP];
__device__ int   g_tok[NSLOT];                // token id per expert slot
__device__ int   g_pair_slot[N_NODES * 2];
__device__ float g_pair_gate[N_NODES * 2];
__device__ float g_h2[(size_t)NSLOT * DIM];   // expert out (fp32)
__device__ float g_y[N_NODES * DIM];          // pre-BN
__device__ float g_colsum[DIM];
__device__ float g_colsumsq[DIM];

// pre-split bf16 hi/lo activations (16B-aligned for cp.async)
__device__ __align__(16) __nv_bfloat16 g_axh[(size_t)N_NODES * 2 * DIM]; // [row][0:256]=m*rs, [256:512]=feats
__device__ __align__(16) __nv_bfloat16 g_axl[(size_t)N_NODES * 2 * DIM];
__device__ __align__(16) __nv_bfloat16 g_xh[(size_t)N_NODES * DIM];
__device__ __align__(16) __nv_bfloat16 g_xl[(size_t)N_NODES * DIM];
__device__ __align__(16) __nv_bfloat16 g_h1h[(size_t)NSLOT * HID];
__device__ __align__(16) __nv_bfloat16 g_h1l[(size_t)NSLOT * HID];

// prepped (transposed + hi/lo split) weights, [n][k] bf16
__device__ __align__(16) __nv_bfloat16 pw1h[(size_t)NEXP * HID * DIM];  // [e][h][d]
__device__ __align__(16) __nv_bfloat16 pw1l[(size_t)NEXP * HID * DIM];
__device__ __align__(16) __nv_bfloat16 pw2h[(size_t)NEXP * DIM * HID];  // [e][d][h]
__device__ __align__(16) __nv_bfloat16 pw2l[(size_t)NEXP * DIM * HID];
__device__ __align__(16) __nv_bfloat16 pgch[DIM * DIM];                 // [n][k]
__device__ __align__(16) __nv_bfloat16 pgcl[DIM * DIM];
__device__ __align__(16) __nv_bfloat16 presh[DIM * DIM];
__device__ __align__(16) __nv_bfloat16 presl[DIM * DIM];

// ---------------- helpers ----------------
__device__ __forceinline__ void splitf(float v, __nv_bfloat16& h, __nv_bfloat16& l) {
    h = __float2bfloat16(v);
    l = __float2bfloat16(v - __bfloat162float(h));
}
__device__ __forceinline__ unsigned pack2(__nv_bfloat16 a, __nv_bfloat16 b) {
    __nv_bfloat162 p = __halves2bfloat162(a, b);   // .x -> low 16 bits (element k)
    return *reinterpret_cast<unsigned*>(&p);
}

__device__ __forceinline__ void cp16(void* sdst, const void* gsrc) {
    unsigned d = (unsigned)__cvta_generic_to_shared(sdst);
    asm volatile("cp.async.cg.shared.global [%0], [%1], 16;" :: "r"(d), "l"(gsrc));
}
#define CP_COMMIT() asm volatile("cp.async.commit_group;")
#define CP_WAIT1()  asm volatile("cp.async.wait_group 1;")

__device__ __forceinline__ void mma_bf16(float* d, const unsigned* a, const unsigned* b) {
    asm volatile(
        "mma.sync.aligned.m16n8k16.row.col.f32.bf16.bf16.f32 "
        "{%0,%1,%2,%3}, {%4,%5,%6,%7}, {%8,%9}, {%0,%1,%2,%3};"
        : "+f"(d[0]), "+f"(d[1]), "+f"(d[2]), "+f"(d[3])
        : "r"(a[0]), "r"(a[1]), "r"(a[2]), "r"(a[3]), "r"(b[0]), "r"(b[1]));
}

// smem: two stages, each 4 arrays of [128][20] uint32 (stride 20 -> conflict-free frags)
#define ARR_W   2560        // 128*20 words
#define STAGE_W 10240       // 4 arrays
#define SMEM_BYTES (2 * STAGE_W * 4)

// 128x128x32 tile step, bf16x3 error-compensated
__device__ __forceinline__ void tile_mma3(
    const unsigned* __restrict__ sAh, const unsigned* __restrict__ sAl,
    const unsigned* __restrict__ sBh, const unsigned* __restrict__ sBl,
    float (*acc)[8][4], int lane, int wm, int wn) {
    const unsigned (*Ah)[20] = (const unsigned(*)[20])sAh;
    const unsigned (*Al)[20] = (const unsigned(*)[20])sAl;
    const unsigned (*Bh)[20] = (const unsigned(*)[20])sBh;
    const unsigned (*Bl)[20] = (const unsigned(*)[20])sBl;
    int g = lane >> 2, c = lane & 3;
#pragma unroll
    for (int ks = 0; ks < 2; ks++) {
        int kp = ks * 8;
        unsigned ah[2][4], al[2][4];
#pragma unroll
        for (int mi = 0; mi < 2; mi++) {
            int rb = wm * 32 + mi * 16;
            ah[mi][0] = Ah[rb + g][kp + c];
            ah[mi][1] = Ah[rb + g + 8][kp + c];
            ah[mi][2] = Ah[rb + g][kp + c + 4];
            ah[mi][3] = Ah[rb + g + 8][kp + c + 4];
            al[mi][0] = Al[rb + g][kp + c];
            al[mi][1] = Al[rb + g + 8][kp + c];
            al[mi][2] = Al[rb + g][kp + c + 4];
            al[mi][3] = Al[rb + g + 8][kp + c + 4];
        }
#pragma unroll
        for (int ni = 0; ni < 8; ni++) {
            int nb = wn * 64 + ni * 8 + g;
            unsigned bh[2] = { Bh[nb][kp + c], Bh[nb][kp + c + 4] };
            unsigned bl[2] = { Bl[nb][kp + c], Bl[nb][kp + c + 4] };
#pragma unroll
            for (int mi = 0; mi < 2; mi++) {
                mma_bf16(acc[mi][ni], ah[mi], bh);
                mma_bf16(acc[mi][ni], ah[mi], bl);
                mma_bf16(acc[mi][ni], al[mi], bh);
            }
        }
    }
}

__device__ __forceinline__ void pref_tile(
    const __nv_bfloat16* __restrict__ ph, const __nv_bfloat16* __restrict__ pl,
    const int* rows, int rbase, int rstride, int kb,
    unsigned* sh, unsigned* sl, int tid) {
#pragma unroll
    for (int i = 0; i < 2; i++) {
        int lin = tid + i * 256;
        int r = lin >> 2, seg = lin & 3;
        int grow = rows ? rows[r] : (rbase + r);
        size_t off = (size_t)grow * rstride + kb + seg * 8;
        cp16(&sh[r * 20 + seg * 4], ph + off);
        cp16(&sl[r * 20 + seg * 4], pl + off);
    }
}

// ---------------- zero everything that is accumulated ----------------
__global__ void k_zero() {
    int idx = blockIdx.x * blockDim.x + threadIdx.x;
    int stride = gridDim.x * blockDim.x;
    for (int i = idx; i < N_NODES * DIM; i += stride) g_m[i] = 0.f;
    if (idx < N_NODES) { g_deg_out[idx] = 0; g_deg_in[idx] = 0; }
    if (idx < NEXP) g_counts[idx] = 0;
    if (idx < DIM) { g_colsum[idx] = 0.f; g_colsumsq[idx] = 0.f; }
}

// ---------------- weight prep: transpose + hi/lo split ----------------
// W: slab-major [z][R][C] fp32  ->  out[z][C][R] bf16 hi/lo
__global__ void k_prep(const float* __restrict__ W, __nv_bfloat16* __restrict__ oh,
                       __nv_bfloat16* __restrict__ ol, int R, int C) {
    __shared__ float t[32][33];
    size_t slab = (size_t)blockIdx.z * R * C;
    int c0 = blockIdx.x * 32, r0 = blockIdx.y * 32;
    int tx = threadIdx.x, ty = threadIdx.y;    // 32 x 8
#pragma unroll
    for (int i = 0; i < 32; i += 8)
        t[ty + i][tx] = W[slab + (size_t)(r0 + ty + i) * C + c0 + tx];
    __syncthreads();
#pragma unroll
    for (int i = 0; i < 32; i += 8) {
        float v = t[tx][ty + i];
        __nv_bfloat16 h, l; splitf(v, h, l);
        size_t o = slab + (size_t)(c0 + ty + i) * R + r0 + tx;
        oh[o] = h; ol[o] = l;
    }
}

// ---------------- activation pre-split, feats half (independent of scatter) ----------------
__global__ void k_prea_feats(const float* __restrict__ feats) {
    int idx = blockIdx.x * blockDim.x + threadIdx.x;   // one per 4 elems
    int lin4 = idx * 4;
    if (lin4 >= N_NODES * DIM) return;
    int row = lin4 >> 8, c = lin4 & 255;
    float4 v = *(const float4*)&feats[(size_t)row * DIM + c];
    __nv_bfloat16 h0,l0,h1,l1,h2,l2,h3,l3;
    splitf(v.x,h0,l0); splitf(v.y,h1,l1); splitf(v.z,h2,l2); splitf(v.w,h3,l3);
    size_t o = (size_t)row * 2 * DIM + DIM + c;
    *(uint2*)&g_axh[o] = make_uint2(pack2(h0,h1), pack2(h2,h3));
    *(uint2*)&g_axl[o] = make_uint2(pack2(l0,l1), pack2(l2,l3));
}

// ---------------- activation pre-split, m half (after scatter+rs) ----------------
__global__ void k_prea_m() {
    int idx = blockIdx.x * blockDim.x + threadIdx.x;   // one per 4 elems
    int lin4 = idx * 4;
    if (lin4 >= N_NODES * DIM) return;
    int row = lin4 >> 8, c = lin4 & 255;
    float4 v = *(const float4*)&g_m[(size_t)row * DIM + c];
    float s = g_rs_in[row];
    v.x *= s; v.y *= s; v.z *= s; v.w *= s;
    __nv_bfloat16 h0,l0,h1,l1,h2,l2,h3,l3;
    splitf(v.x,h0,l0); splitf(v.y,h1,l1); splitf(v.z,h2,l2); splitf(v.w,h3,l3);
    size_t o = (size_t)row * 2 * DIM + c;
    *(uint2*)&g_axh[o] = make_uint2(pack2(h0,h1), pack2(h2,h3));
    *(uint2*)&g_axl[o] = make_uint2(pack2(l0,l1), pack2(l2,l3));
}

// ---------------- degree counts ----------------
__global__ void k_deg(const int* __restrict__ src, const int* __restrict__ dst) {
    int e = blockIdx.x * blockDim.x + threadIdx.x;
    if (e < N_EDGES) {
        atomicAdd(&g_deg_out[src[e]], 1);
        atomicAdd(&g_deg_in[dst[e]], 1);
    }
}

__global__ void k_rs() {
    int i = blockIdx.x * blockDim.x + threadIdx.x;
    if (i < N_NODES) {
        g_rs_out[i] = rsqrtf((float)max(g_deg_out[i], 1));
        g_rs_in[i]  = rsqrtf((float)max(g_deg_in[i], 1));
    }
}

// ---------------- edge scatter: m[dst] += feats[src] * rs_out[src] ----------------
__global__ void k_scatter(const float* __restrict__ feats,
                          const int* __restrict__ src, const int* __restrict__ dst) {
    int warp = (blockIdx.x * blockDim.x + threadIdx.x) >> 5;
    int lane = threadIdx.x & 31;
    if (warp >= N_EDGES) return;
    int s = src[warp], d = dst[warp];
    float sc = g_rs_out[s];
    const float4* fr = (const float4*)(feats + (size_t)s * DIM);
    float* mr = g_m + (size_t)d * DIM;
#pragma unroll
    for (int i = 0; i < 2; i++) {
        int j = lane + i * 32;           // 64 float4 per row
        float4 v = __ldg(&fr[j]);
        v.x *= sc; v.y *= sc; v.z *= sc; v.w *= sc;
        asm volatile("red.global.add.v4.f32 [%0], {%1,%2,%3,%4};"
                     :: "l"(mr + j * 4), "f"(v.x), "f"(v.y), "f"(v.z), "f"(v.w)
                     : "memory");
    }
}

// ---------------- x = ax @ [Wgc;Wres] + bgc + bres  (bf16x3 pipelined, K=512) ----------------
__global__ __launch_bounds__(256) void k_xgemm(
    const float* __restrict__ bgc, const float* __restrict__ bres) {
    extern __shared__ unsigned sm[];
    int tid = threadIdx.x, lane = tid & 31, wid = tid >> 5;
    int wm = wid & 3, wn = wid >> 2;
    int row0 = blockIdx.y * 128, col0 = blockIdx.x * 128;
    float acc[2][8][4] = {};
    const int NCH = 2 * DIM / 32;   // 16

    {
        unsigned* s0 = sm;
        pref_tile(g_axh, g_axl, nullptr, row0, 2 * DIM, 0, s0, s0 + ARR_W, tid);
        pref_tile(pgch, pgcl, nullptr, col0, DIM, 0, s0 + 2 * ARR_W, s0 + 3 * ARR_W, tid);
    }
    CP_COMMIT();

    for (int ch = 0; ch < NCH; ch++) {
        int cur = ch & 1;
        if (ch + 1 < NCH) {
            unsigned* s = sm + (cur ^ 1) * STAGE_W;
            int kb = (ch + 1) * 32;
            pref_tile(g_axh, g_axl, nullptr, row0, 2 * DIM, kb, s, s + ARR_W, tid);
            if (kb < DIM)
                pref_tile(pgch, pgcl, nullptr, col0, DIM, kb, s + 2 * ARR_W, s + 3 * ARR_W, tid);
            else
                pref_tile(presh, presl, nullptr, col0, DIM, kb - DIM, s + 2 * ARR_W, s + 3 * ARR_W, tid);
        }
        CP_COMMIT();
        CP_WAIT1();
        __syncthreads();
        unsigned* s = sm + cur * STAGE_W;
        tile_mma3(s, s + ARR_W, s + 2 * ARR_W, s + 3 * ARR_W, acc, lane, wm, wn);
        __syncthreads();
    }

    int g = lane >> 2, c2 = (lane & 3) * 2;
#pragma unroll
    for (int mi = 0; mi < 2; mi++) {
        int r = row0 + wm * 32 + mi * 16 + g;
#pragma unroll
        for (int ni = 0; ni < 8; ni++) {
            int col = col0 + wn * 64 + ni * 8 + c2;
            float b0 = bgc[col] + bres[col], b1 = bgc[col + 1] + bres[col + 1];
            float v00 = acc[mi][ni][0] + b0, v01 = acc[mi][ni][1] + b1;
            float v10 = acc[mi][ni][2] + b0, v11 = acc[mi][ni][3] + b1;
            *(float2*)&g_x[(size_t)r * DIM + col] = make_float2(v00, v01);
            *(float2*)&g_x[(size_t)(r + 8) * DIM + col] = make_float2(v10, v11);
            __nv_bfloat16 h0,l0,h1,l1;
            splitf(v00,h0,l0); splitf(v01,h1,l1);
            *(unsigned*)&g_xh[(size_t)r * DIM + col] = pack2(h0,h1);
            *(unsigned*)&g_xl[(size_t)r * DIM + col] = pack2(l0,l1);
            splitf(v10,h0,l0); splitf(v11,h1,l1);
            *(unsigned*)&g_xh[(size_t)(r + 8) * DIM + col] = pack2(h0,h1);
            *(unsigned*)&g_xl[(size_t)(r + 8) * DIM + col] = pack2(l0,l1);
        }
    }
}

// ---------------- gating: warp per token, top-2 + softmax, slot assignment ----------------
__global__ void k_gate(const float* __restrict__ Wg, const float* __restrict__ bg) {
    int t = (blockIdx.x * blockDim.x + threadIdx.x) >> 5;
    int lane = threadIdx.x & 31;
    if (t >= N_NODES) return;
    const float* xr = g_x + (size_t)t * DIM;
    float la = bg[lane], lb = bg[lane + 32];
    for (int k = 0; k < DIM; k++) {
        float xv = xr[k];
        la = fmaf(xv, Wg[k * NEXP + lane], la);
        lb = fmaf(xv, Wg[k * NEXP + lane + 32], lb);
    }
    float bv = la; int bi = lane;
    if (lb > bv) { bv = lb; bi = lane + 32; }
#pragma unroll
    for (int off = 16; off; off >>= 1) {
        float ov = __shfl_xor_sync(0xffffffffu, bv, off);
        int   oi = __shfl_xor_sync(0xffffffffu, bi, off);
        if (ov > bv || (ov == bv && oi < bi)) { bv = ov; bi = oi; }
    }
    float v0 = bv; int e0 = bi;
    float ca = (lane == e0) ? -INFINITY : la;
    float cb = (lane + 32 == e0) ? -INFINITY : lb;
    float bv2 = ca; int bi2 = lane;
    if (cb > bv2) { bv2 = cb; bi2 = lane + 32; }
#pragma unroll
    for (int off = 16; off; off >>= 1) {
        float ov = __shfl_xor_sync(0xffffffffu, bv2, off);
        int   oi = __shfl_xor_sync(0xffffffffu, bi2, off);
        if (ov > bv2 || (ov == bv2 && oi < bi2)) { bv2 = ov; bi2 = oi; }
    }
    float v1 = bv2; int e1 = bi2;
    if (lane == 0) {
        float g0 = 1.f / (1.f + expf(v1 - v0));
        float g1 = 1.f - g0;
        int r0 = atomicAdd(&g_counts[e0], 1);
        int s0 = (r0 < CAP) ? e0 * CAP + r0 : -1;
        if (s0 >= 0) g_tok[s0] = t;
        g_pair_slot[2 * t] = s0; g_pair_gate[2 * t] = g0;
        int r1 = atomicAdd(&g_counts[e1], 1);
        int s1 = (r1 < CAP) ? e1 * CAP + r1 : -1;
        if (s1 >= 0) g_tok[s1] = t;
        g_pair_slot[2 * t + 1] = s1; g_pair_gate[2 * t + 1] = g1;
    }
}

// ---------------- FFN1: h1 = gelu(gather(x) @ w1[e] + b1[e])  (bf16x3 pipelined) ----------------
__global__ __launch_bounds__(256) void k_ffn1(const float* __restrict__ b1) {
    int e = blockIdx.z;
    int cnt = min(g_counts[e], CAP);
    int row0 = blockIdx.y * 128;
    if (row0 >= cnt) return;
    int col0 = blockIdx.x * 128;
    const __nv_bfloat16* ph = pw1h + (size_t)e * HID * DIM;   // [h][d]
    const __nv_bfloat16* pl = pw1l + (size_t)e * HID * DIM;
    extern __shared__ unsigned sm[];
    __shared__ int stok[128];
    int tid = threadIdx.x, lane = tid & 31, wid = tid >> 5;
    int wm = wid & 3, wn = wid >> 2;
    if (tid < 128) {
        int rr = row0 + tid;
        stok[tid] = (rr < cnt) ? g_tok[e * CAP + rr] : 0;
    }
    __syncthreads();
    float acc[2][8][4] = {};
    const int NCH = DIM / 32;   // 8

    {
        unsigned* s0 = sm;
        pref_tile(g_xh, g_xl, stok, 0, DIM, 0, s0, s0 + ARR_W, tid);
        pref_tile(ph, pl, nullptr, col0, DIM, 0, s0 + 2 * ARR_W, s0 + 3 * ARR_W, tid);
    }
    CP_COMMIT();

    for (int ch = 0; ch < NCH; ch++) {
        int cur = ch & 1;
        if (ch + 1 < NCH) {
            unsigned* s = sm + (cur ^ 1) * STAGE_W;
            int kb = (ch + 1) * 32;
            pref_tile(g_xh, g_xl, stok, 0, DIM, kb, s, s + ARR_W, tid);
            pref_tile(ph, pl, nullptr, col0, DIM, kb, s + 2 * ARR_W, s + 3 * ARR_W, tid);
        }
        CP_COMMIT();
        CP_WAIT1();
        __syncthreads();
        unsigned* s = sm + cur * STAGE_W;
        tile_mma3(s, s + ARR_W, s + 2 * ARR_W, s + 3 * ARR_W, acc, lane, wm, wn);
        __syncthreads();
    }

    int g = lane >> 2, c2 = (lane & 3) * 2;
#pragma unroll
    for (int mi = 0; mi < 2; mi++) {
        int rl = wm * 32 + mi * 16 + g;
#pragma unroll
        for (int ni = 0; ni < 8; ni++) {
            int col = col0 + wn * 64 + ni * 8 + c2;
            float b0 = b1[e * HID + col], bb1 = b1[e * HID + col + 1];
#pragma unroll
            for (int h = 0; h < 2; h++) {
                int rr = row0 + rl + h * 8;
                if (rr < cnt) {
                    float v0 = acc[mi][ni][2 * h] + b0;
                    float v1 = acc[mi][ni][2 * h + 1] + bb1;
                    float o0 = 0.5f * v0 * (1.f + erff(v0 * 0.70710678118654752440f));
                    float o1 = 0.5f * v1 * (1.f + erff(v1 * 0.70710678118654752440f));
                    __nv_bfloat16 hh0,ll0,hh1,ll1;
                    splitf(o0,hh0,ll0); splitf(o1,hh1,ll1);
                    size_t off = (size_t)(e * CAP + rr) * HID + col;
                    *(unsigned*)&g_h1h[off] = pack2(hh0,hh1);
                    *(unsigned*)&g_h1l[off] = pack2(ll0,ll1);
                }
            }
        }
    }
}

// ---------------- FFN2: h2 = h1 @ w2[e] + b2[e]  (bf16x3 pipelined) ----------------
__global__ __launch_bounds__(256) void k_ffn2(const float* __restrict__ b2) {
    int e = blockIdx.z;
    int cnt = min(g_counts[e], CAP);
    int row0 = blockIdx.y * 128;
    if (row0 >= cnt) return;
    int col0 = blockIdx.x * 128;
    const __nv_bfloat16* ph = pw2h + (size_t)e * DIM * HID;   // [d][h]
    const __nv_bfloat16* pl = pw2l + (size_t)e * DIM * HID;
    extern __shared__ unsigned sm[];
    int tid = threadIdx.x, lane = tid & 31, wid = tid >> 5;
    int wm = wid & 3, wn = wid >> 2;
    int abase = e * CAP + row0;
    float acc[2][8][4] = {};
    const int NCH = HID / 32;   // 16

    {
        unsigned* s0 = sm;
        pref_tile(g_h1h, g_h1l, nullptr, abase, HID, 0, s0, s0 + ARR_W, tid);
        pref_tile(ph, pl, nullptr, col0, HID, 0, s0 + 2 * ARR_W, s0 + 3 * ARR_W, tid);
    }
    CP_COMMIT();

    for (int ch = 0; ch < NCH; ch++) {
        int cur = ch & 1;
        if (ch + 1 < NCH) {
            unsigned* s = sm + (cur ^ 1) * STAGE_W;
            int kb = (ch + 1) * 32;
            pref_tile(g_h1h, g_h1l, nullptr, abase, HID, kb, s, s + ARR_W, tid);
            pref_tile(ph, pl, nullptr, col0, HID, kb, s + 2 * ARR_W, s + 3 * ARR_W, tid);
        }
        CP_COMMIT();
        CP_WAIT1();
        __syncthreads();
        unsigned* s = sm + cur * STAGE_W;
        tile_mma3(s, s + ARR_W, s + 2 * ARR_W, s + 3 * ARR_W, acc, lane, wm, wn);
        __syncthreads();
    }

    int g = lane >> 2, c2 = (lane & 3) * 2;
#pragma unroll
    for (int mi = 0; mi < 2; mi++) {
        int rl = wm * 32 + mi * 16 + g;
#pragma unroll
        for (int ni = 0; ni < 8; ni++) {
            int col = col0 + wn * 64 + ni * 8 + c2;
            float b0 = b2[e * DIM + col], bb1 = b2[e * DIM + col + 1];
#pragma unroll
            for (int h = 0; h < 2; h++) {
                int rr = row0 + rl + h * 8;
                if (rr < cnt) {
                    *(float2*)&g_h2[(size_t)(e * CAP + rr) * DIM + col] =
                        make_float2(acc[mi][ni][2 * h] + b0, acc[mi][ni][2 * h + 1] + bb1);
                }
            }
        }
    }
}

// ---------------- combine: y = x + g0*h2[s0] + g1*h2[s1]; column sums for BN ----------------
__global__ void k_combine() {
    int c = threadIdx.x;                 // 256 threads = 256 columns
    int t0 = blockIdx.x * 128;
    float sum = 0.f, sumsq = 0.f;
    for (int i = 0; i < 128; i++) {
        int t = t0 + i;
        int s0 = g_pair_slot[2 * t], s1 = g_pair_slot[2 * t + 1];
        float g0 = g_pair_gate[2 * t], g1 = g_pair_gate[2 * t + 1];
        float v = g_x[(size_t)t * DIM + c];
        if (s0 >= 0) v += g0 * g_h2[(size_t)s0 * DIM + c];
        if (s1 >= 0) v += g1 * g_h2[(size_t)s1 * DIM + c];
        g_y[(size_t)t * DIM + c] = v;
        sum += v; sumsq += v * v;
    }
    atomicAdd(&g_colsum[c], sum);
    atomicAdd(&g_colsumsq[c], sumsq);
}

// ---------------- batchnorm (train-mode, biased var) ----------------
__global__ void k_bn(const float* __restrict__ gamma, const float* __restrict__ beta,
                     float* __restrict__ out) {
    int idx = blockIdx.x * blockDim.x + threadIdx.x;
    if (idx >= N_NODES * DIM) return;
    int c = idx & (DIM - 1);
    const float invN = 1.f / (float)N_NODES;
    float mean = g_colsum[c] * invN;
    float var = g_colsumsq[c] * invN - mean * mean;
    out[idx] = (g_y[idx] - mean) * rsqrtf(var + BN_EPS) * gamma[c] + beta[c];
}

// ---------------- launcher ----------------
extern "C" void kernel_launch(void* const* d_in, const int* in_sizes, int n_in,
                              void* d_out, int out_size) {
    const float* feats = (const float*)d_in[0];
    const float* Wgc   = (const float*)d_in[1];
    const float* bgc   = (const float*)d_in[2];
    const float* Wres  = (const float*)d_in[3];
    const float* bres  = (const float*)d_in[4];
    const float* Wg    = (const float*)d_in[5];
    const float* bg    = (const float*)d_in[6];
    const float* w1    = (const float*)d_in[7];
    const float* b1    = (const float*)d_in[8];
    const float* w2    = (const float*)d_in[9];
    const float* b2    = (const float*)d_in[10];
    const float* gamma = (const float*)d_in[11];
    const float* beta  = (const float*)d_in[12];
    const int*   src   = (const int*)d_in[13];
    const int*   dst   = (const int*)d_in[14];
    float* out = (float*)d_out;

    __nv_bfloat16 *d_pw1h, *d_pw1l, *d_pw2h, *d_pw2l, *d_pgch, *d_pgcl, *d_presh, *d_presl;
    cudaGetSymbolAddress((void**)&d_pw1h, pw1h);
    cudaGetSymbolAddress((void**)&d_pw1l, pw1l);
    cudaGetSymbolAddress((void**)&d_pw2h, pw2h);
    cudaGetSymbolAddress((void**)&d_pw2l, pw2l);
    cudaGetSymbolAddress((void**)&d_pgch, pgch);
    cudaGetSymbolAddress((void**)&d_pgcl, pgcl);
    cudaGetSymbolAddress((void**)&d_presh, presh);
    cudaGetSymbolAddress((void**)&d_presl, presl);

    cudaFuncSetAttribute(k_xgemm, cudaFuncAttributeMaxDynamicSharedMemorySize, SMEM_BYTES);
    cudaFuncSetAttribute(k_ffn1,  cudaFuncAttributeMaxDynamicSharedMemorySize, SMEM_BYTES);
    cudaFuncSetAttribute(k_ffn2,  cudaFuncAttributeMaxDynamicSharedMemorySize, SMEM_BYTES);

    // side stream + events (created once; host-side objects, no device allocation)
    static cudaStream_t s1 = nullptr;
    static cudaEvent_t ev_fork = nullptr, ev_join = nullptr;
    if (!s1) {
        cudaStreamCreateWithFlags(&s1, cudaStreamNonBlocking);
        cudaEventCreateWithFlags(&ev_fork, cudaEventDisableTiming);
        cudaEventCreateWithFlags(&ev_join, cudaEventDisableTiming);
    }

    dim3 tb(32, 8);

    // fork: side stream does weight prep + feats pre-split, concurrent with graph chain
    cudaEventRecord(ev_fork, 0);
    cudaStreamWaitEvent(s1, ev_fork, 0);
    k_prep<<<dim3(HID / 32, DIM / 32, NEXP), tb, 0, s1>>>(w1, d_pw1h, d_pw1l, DIM, HID);
    k_prep<<<dim3(DIM / 32, HID / 32, NEXP), tb, 0, s1>>>(w2, d_pw2h, d_pw2l, HID, DIM);
    k_prep<<<dim3(DIM / 32, DIM / 32, 1),    tb, 0, s1>>>(Wgc,  d_pgch,  d_pgcl,  DIM, DIM);
    k_prep<<<dim3(DIM / 32, DIM / 32, 1),    tb, 0, s1>>>(Wres, d_presh, d_presl, DIM, DIM);
    k_prea_feats<<<(N_NODES * DIM / 4 + 255) / 256, 256, 0, s1>>>(feats);
    cudaEventRecord(ev_join, s1);

    // main chain on legacy stream
    k_zero<<<4096, 256>>>();
    k_deg<<<N_EDGES / 256, 256>>>(src, dst);
    k_rs<<<N_NODES / 256, 256>>>();
    k_scatter<<<N_EDGES / 8, 256>>>(feats, src, dst);      // 1 warp / edge
    k_prea_m<<<(N_NODES * DIM / 4 + 255) / 256, 256>>>();

    // join: xgemm needs prepped gc/res weights + both prea halves
    cudaStreamWaitEvent(0, ev_join, 0);
    k_xgemm<<<dim3(DIM / 128, N_NODES / 128), 256, SMEM_BYTES>>>(bgc, bres);
    k_gate<<<N_NODES / 8, 256>>>(Wg, bg);
    k_ffn1<<<dim3(HID / 128, CAP / 128, NEXP), 256, SMEM_BYTES>>>(b1);
    k_ffn2<<<dim3(DIM / 128, CAP / 128, NEXP), 256, SMEM_BYTES>>>(b2);
    k_combine<<<N_NODES / 128, 256>>>();
    k_bn<<<(N_NODES * DIM) / 256, 256>>>(gamma, beta, out);
}